// round 14
// baseline (speedup 1.0000x reference)
#include <cuda_runtime.h>
#include <cuda_bf16.h>
#include <cstdint>

#define NSEQ 1024
#define DIM  256
#define HEADS 8
#define EDIM 512
#define HD   64
#define PEC  32
#define BH   32           // B*HEADS
#define ROWS 4096         // B*N

// ---------------- scratch (device globals; no runtime allocation) ----------
__device__ __nv_bfloat16 g_xh[ROWS * DIM], g_xl[ROWS * DIM];
__device__ __nv_bfloat16 g_wth[1536 * 256], g_wtl[1536 * 256];   // [n][k]
__device__ __nv_bfloat16 g_wpth[256 * 512], g_wptl[256 * 512];   // [n][k]
__device__ __nv_bfloat16 g_qh[BH * NSEQ * HD];
__device__ __nv_bfloat16 g_ql[BH * NSEQ * HD];
__device__ __nv_bfloat16 g_kh[BH * NSEQ * HD];
__device__ __nv_bfloat16 g_kl[BH * NSEQ * HD];
__device__ __nv_bfloat16 g_vth[BH * HD * NSEQ];   // transposed: [bh][d][n]
__device__ __nv_bfloat16 g_vtl[BH * HD * NSEQ];
__device__ __nv_bfloat16 g_attn_h[(size_t)BH * NSEQ * NSEQ];  // 64 MB
__device__ float g_oh[BH * NSEQ * HD];
__device__ float g_pes[BH * NSEQ * PEC];
__device__ __nv_bfloat16 g_mh[ROWS * EDIM], g_ml[ROWS * EDIM];

union B16x8 { __nv_bfloat16 h[8]; uint4 u; };
union B16x4 { __nv_bfloat16 h[4]; uint2 u; };
union B16x2 { __nv_bfloat16 h[2]; uint32_t u; };

__device__ __forceinline__ void split2(float x, __nv_bfloat16& h, __nv_bfloat16& l) {
  h = __float2bfloat16_rn(x);
  l = __float2bfloat16_rn(x - __bfloat162float(h));
}

// m16n8k16 bf16 mma with fp32 accumulate (row.col)
__device__ __forceinline__ void mma16816(float* c, const uint32_t* a,
                                         const uint32_t* b) {
  asm volatile(
      "mma.sync.aligned.m16n8k16.row.col.f32.bf16.bf16.f32 "
      "{%0,%1,%2,%3}, {%4,%5,%6,%7}, {%8,%9}, {%0,%1,%2,%3};"
      : "+f"(c[0]), "+f"(c[1]), "+f"(c[2]), "+f"(c[3])
      : "r"(a[0]), "r"(a[1]), "r"(a[2]), "r"(a[3]), "r"(b[0]), "r"(b[1]));
}

// ldmatrix x4: 4 8x8 b16 tiles; lane group g=lane>>3 supplies address of tile g
__device__ __forceinline__ void ldsm4(uint32_t* d, const __nv_bfloat16* p) {
  uint32_t a = (uint32_t)__cvta_generic_to_shared(p);
  asm volatile("ldmatrix.sync.aligned.m8n8.x4.shared.b16 {%0,%1,%2,%3}, [%4];"
               : "=r"(d[0]), "=r"(d[1]), "=r"(d[2]), "=r"(d[3]) : "r"(a));
}

// 16B async copy gmem -> smem
__device__ __forceinline__ void cp16(__nv_bfloat16* smem_ptr, const __nv_bfloat16* gptr) {
  uint32_t s = (uint32_t)__cvta_generic_to_shared(smem_ptr);
  asm volatile("cp.async.cg.shared.global [%0], [%1], 16;" :: "r"(s), "l"(gptr));
}
#define CP_COMMIT() asm volatile("cp.async.commit_group;" ::: "memory")
#define CP_WAIT1()  asm volatile("cp.async.wait_group 1;" ::: "memory")
#define CP_WAIT0()  asm volatile("cp.async.wait_group 0;" ::: "memory")

#define LDSTRIDE 72   // bf16 units per SMEM row (64 data + 8 pad)
#define PSTRIDE 136   // bf16 units per SMEM row (128 data + 8 pad)

// ---------------- prep: split x + transpose/split weights (fused) -----------
__global__ __launch_bounds__(256) void prep_all(
    const float* __restrict__ x, const float* __restrict__ Wq,
    const float* __restrict__ Wk, const float* __restrict__ Wv,
    const float* __restrict__ Wproj) {
  if (blockIdx.x < 1024) {
    int idx = (blockIdx.x * 256 + threadIdx.x) * 4;
    float4 v = *(const float4*)(x + idx);
    B16x4 hh, ll;
    split2(v.x, hh.h[0], ll.h[0]); split2(v.y, hh.h[1], ll.h[1]);
    split2(v.z, hh.h[2], ll.h[2]); split2(v.w, hh.h[3], ll.h[3]);
    *(uint2*)&g_xh[idx] = hh.u;
    *(uint2*)&g_xl[idx] = ll.u;
    return;
  }
  int id = (blockIdx.x - 1024) * 256 + threadIdx.x;
  if (id < 98304) {                 // WT: 1536 n x 64 k-groups
    int n = id >> 6, k0 = (id & 63) * 4;
    int sel = n >> 9, col = n & 511;
    const float* W = (sel == 0) ? Wq : (sel == 1) ? Wk : Wv;
#pragma unroll
    for (int q = 0; q < 4; q++) {
      float v = W[(k0 + q) * 512 + col];
      split2(v, g_wth[n * 256 + k0 + q], g_wtl[n * 256 + k0 + q]);
    }
  } else {                          // WprojT: 256 n x 128 k-groups
    int id2 = id - 98304;
    int n = id2 >> 7, k0 = (id2 & 127) * 4;
#pragma unroll
    for (int q = 0; q < 4; q++) {
      float v = Wproj[(k0 + q) * 256 + n];
      split2(v, g_wpth[n * 512 + k0 + q], g_wptl[n * 512 + k0 + q]);
    }
  }
}

// ---------------- Kernel 1: QKV projection (cp.async pipelined) -------------
// M=4096, N=1536, K=256. CTA 128m x 64n, grid (32, 24). 8 warps: 4m x 2n.
#define QKV_X (128 * LDSTRIDE)   // per array
#define QKV_W (64 * LDSTRIDE)
#define QKV_STAGE (2 * QKV_X + 2 * QKV_W)     // 27648 elems per stage
#define QKV_SMEM_BYTES (2 * QKV_STAGE * 2)    // 110592 B
__global__ __launch_bounds__(256) void qkv_mma(const float* __restrict__ bv) {
  extern __shared__ __nv_bfloat16 sm[];

  int tid = threadIdx.x;
  int wid = tid >> 5, lane = tid & 31;
  int m0 = blockIdx.x * 128;
  int n0 = blockIdx.y * 64;
  int sel = n0 / 512;
  int e0 = n0 % 512;
  int h = e0 / 64;

  int m_w = (wid >> 1) * 32, n_w = (wid & 1) * 32;
  int r = lane >> 2;
  int g = lane >> 3, rw = lane & 7;

  auto stage = [&](int ck, int s) {
    __nv_bfloat16* base = sm + s * QKV_STAGE;
#pragma unroll
    for (int t = 0; t < 4; t++) {
      int idx = tid + 256 * t;
      int rr = idx >> 3, seg = idx & 7;
      int so = rr * LDSTRIDE + seg * 8;
      size_t gs = (size_t)(m0 + rr) * 256 + ck * 64 + seg * 8;
      cp16(base + so, g_xh + gs);
      cp16(base + QKV_X + so, g_xl + gs);
    }
#pragma unroll
    for (int t = 0; t < 2; t++) {
      int idx = tid + 256 * t;
      int d = idx >> 3, seg = idx & 7;
      int so = 2 * QKV_X + d * LDSTRIDE + seg * 8;
      size_t gs = (size_t)(n0 + d) * 256 + ck * 64 + seg * 8;
      cp16(base + so, g_wth + gs);
      cp16(base + QKV_W + so, g_wtl + gs);
    }
  };

  float c[2][4][4];
#pragma unroll
  for (int mt = 0; mt < 2; mt++)
#pragma unroll
    for (int nt = 0; nt < 4; nt++)
#pragma unroll
      for (int e = 0; e < 4; e++) c[mt][nt][e] = 0.f;

  stage(0, 0);
  CP_COMMIT();

  for (int ck = 0; ck < 4; ck++) {
    int st = ck & 1;
    if (ck < 3) { stage(ck + 1, st ^ 1); CP_COMMIT(); CP_WAIT1(); }
    else CP_WAIT0();
    __syncthreads();
    const __nv_bfloat16* XH = sm + st * QKV_STAGE;
    const __nv_bfloat16* XL = XH + QKV_X;
    const __nv_bfloat16* WH = XL + QKV_X;
    const __nv_bfloat16* WL = WH + QKV_W;
#pragma unroll
    for (int kb = 0; kb < 64; kb += 16) {
      uint32_t ah[2][4], al[2][4];
#pragma unroll
      for (int mt = 0; mt < 2; mt++) {
        ldsm4(ah[mt], XH + (m_w + mt * 16 + (g & 1) * 8 + rw) * LDSTRIDE + kb + (g >> 1) * 8);
        ldsm4(al[mt], XL + (m_w + mt * 16 + (g & 1) * 8 + rw) * LDSTRIDE + kb + (g >> 1) * 8);
      }
      uint32_t bh4[2][4], bl4[2][4];
#pragma unroll
      for (int p = 0; p < 2; p++) {
        ldsm4(bh4[p], WH + (n_w + p * 16 + (g >> 1) * 8 + rw) * LDSTRIDE + kb + (g & 1) * 8);
        ldsm4(bl4[p], WL + (n_w + p * 16 + (g >> 1) * 8 + rw) * LDSTRIDE + kb + (g & 1) * 8);
      }
#pragma unroll
      for (int mt = 0; mt < 2; mt++)
#pragma unroll
        for (int p = 0; p < 2; p++) {
          mma16816(c[mt][2 * p], ah[mt], bh4[p]);
          mma16816(c[mt][2 * p], ah[mt], bl4[p]);
          mma16816(c[mt][2 * p], al[mt], bh4[p]);
          mma16816(c[mt][2 * p + 1], ah[mt], bh4[p] + 2);
          mma16816(c[mt][2 * p + 1], ah[mt], bl4[p] + 2);
          mma16816(c[mt][2 * p + 1], al[mt], bh4[p] + 2);
        }
    }
    __syncthreads();
  }

#pragma unroll
  for (int mt = 0; mt < 2; mt++) {
#pragma unroll
    for (int nt = 0; nt < 4; nt++) {
      int colw = n_w + nt * 8 + (lane & 3) * 2;   // 0..62, even
      int d = colw;                                // channel within head
      int e = e0 + colw;
#pragma unroll
      for (int half = 0; half < 2; half++) {
        int row = m0 + m_w + mt * 16 + r + half * 8;
        float v0 = c[mt][nt][half * 2 + 0];
        float v1 = c[mt][nt][half * 2 + 1];
        int b = row >> 10, n = row & 1023;
        int bh = b * 8 + h;
        if (sel == 0) {
          v0 *= 0.125f; v1 *= 0.125f;
          B16x2 hp, lp;
          split2(v0, hp.h[0], lp.h[0]); split2(v1, hp.h[1], lp.h[1]);
          size_t idx = ((size_t)bh * 1024 + n) * 64 + d;
          *(uint32_t*)&g_qh[idx] = hp.u;
          *(uint32_t*)&g_ql[idx] = lp.u;
        } else if (sel == 1) {
          B16x2 hp, lp;
          split2(v0, hp.h[0], lp.h[0]); split2(v1, hp.h[1], lp.h[1]);
          size_t idx = ((size_t)bh * 1024 + n) * 64 + d;
          *(uint32_t*)&g_kh[idx] = hp.u;
          *(uint32_t*)&g_kl[idx] = lp.u;
        } else {
          v0 += bv[e]; v1 += bv[e + 1];
          __nv_bfloat16 hh, ll;
          split2(v0, hh, ll);
          size_t i0v = ((size_t)bh * 64 + d) * 1024 + n;
          g_vth[i0v] = hh; g_vtl[i0v] = ll;
          split2(v1, hh, ll);
          size_t i1v = ((size_t)bh * 64 + d + 1) * 1024 + n;
          g_vth[i1v] = hh; g_vtl[i1v] = ll;
        }
      }
    }
  }
}

// ---------------- Kernel 2: fused scores + softmax (16-row CTAs) ------------
#define KSTAGE (128 * LDSTRIDE)     // 9216 elements per K stage
#define SM_SMEM_BYTES ((2 * 16 * LDSTRIDE + 2 * KSTAGE) * 2)   // 41472 B
__global__ __launch_bounds__(256, 2) void scoresm() {
  extern __shared__ __nv_bfloat16 smd[];
  __nv_bfloat16* QH = smd;
  __nv_bfloat16* QL = QH + 16 * LDSTRIDE;
  __nv_bfloat16* KHb = QL + 16 * LDSTRIDE;   // 2 stages of KSTAGE
  __shared__ float red[16][8];

  int tid = threadIdx.x;
  int wid = tid >> 5, lane = tid & 31;
  int bh = blockIdx.y;
  int i0 = blockIdx.x * 16;

  const __nv_bfloat16* qh = g_qh + (size_t)bh * NSEQ * HD;
  const __nv_bfloat16* ql = g_ql + (size_t)bh * NSEQ * HD;
  const __nv_bfloat16* kh = g_kh + (size_t)bh * NSEQ * HD;

  if (tid < 128) {
    int r = tid >> 3, seg = tid & 7;
    int so = r * LDSTRIDE + seg * 8;
    *(uint4*)(QH + so) = *(const uint4*)(qh + (i0 + r) * 64 + seg * 8);
    *(uint4*)(QL + so) = *(const uint4*)(ql + (i0 + r) * 64 + seg * 8);
  }
#pragma unroll
  for (int t = 0; t < 4; t++) {
    int idx = tid + 256 * t;
    int rr = idx >> 3, seg = idx & 7;
    cp16(KHb + rr * LDSTRIDE + seg * 8, kh + rr * 64 + seg * 8);
  }
  CP_COMMIT();

  int nwb = wid * 16;
  int r = lane >> 2;
  int g = lane >> 3, rw = lane & 7;

  uint32_t ah[4][4], al[4][4];
  float acc[8][2][4];
#pragma unroll
  for (int jc = 0; jc < 8; jc++)
#pragma unroll
    for (int nt = 0; nt < 2; nt++)
#pragma unroll
      for (int e = 0; e < 4; e++) acc[jc][nt][e] = 0.f;

#pragma unroll
  for (int jc = 0; jc < 8; jc++) {
    int st = jc & 1;
    if (jc < 7) {
      int sn = st ^ 1;
#pragma unroll
      for (int t = 0; t < 4; t++) {
        int idx = tid + 256 * t;
        int rr = idx >> 3, seg = idx & 7;
        cp16(KHb + sn * KSTAGE + rr * LDSTRIDE + seg * 8,
             kh + ((jc + 1) * 128 + rr) * 64 + seg * 8);
      }
      CP_COMMIT();
      CP_WAIT1();
    } else {
      CP_WAIT0();
    }
    __syncthreads();
    const __nv_bfloat16* KH = KHb + st * KSTAGE;
    if (jc == 0) {
#pragma unroll
      for (int kb = 0; kb < 4; kb++) {
        ldsm4(ah[kb], QH + ((g & 1) * 8 + rw) * LDSTRIDE + kb * 16 + (g >> 1) * 8);
        ldsm4(al[kb], QL + ((g & 1) * 8 + rw) * LDSTRIDE + kb * 16 + (g >> 1) * 8);
      }
    }
#pragma unroll
    for (int kb = 0; kb < 4; kb++) {
      uint32_t b4[4];
      ldsm4(b4, KH + (nwb + (g >> 1) * 8 + rw) * LDSTRIDE + kb * 16 + (g & 1) * 8);
      mma16816(acc[jc][0], ah[kb], b4);
      mma16816(acc[jc][0], al[kb], b4);
      mma16816(acc[jc][1], ah[kb], b4 + 2);
      mma16816(acc[jc][1], al[kb], b4 + 2);
    }
    __syncthreads();
  }

  int r0 = r, r1 = r0 + 8;
  float m0 = -1e30f, m1 = -1e30f;
#pragma unroll
  for (int jc = 0; jc < 8; jc++)
#pragma unroll
    for (int nt = 0; nt < 2; nt++) {
      m0 = fmaxf(m0, fmaxf(acc[jc][nt][0], acc[jc][nt][1]));
      m1 = fmaxf(m1, fmaxf(acc[jc][nt][2], acc[jc][nt][3]));
    }
#pragma unroll
  for (int o = 1; o <= 2; o <<= 1) {
    m0 = fmaxf(m0, __shfl_xor_sync(~0u, m0, o));
    m1 = fmaxf(m1, __shfl_xor_sync(~0u, m1, o));
  }
  if ((lane & 3) == 0) { red[r0][wid] = m0; red[r1][wid] = m1; }
  __syncthreads();
#pragma unroll
  for (int q = 0; q < 8; q++) {
    m0 = fmaxf(m0, red[r0][q]);
    m1 = fmaxf(m1, red[r1][q]);
  }
  __syncthreads();

  float s0 = 0.f, s1 = 0.f;
#pragma unroll
  for (int jc = 0; jc < 8; jc++)
#pragma unroll
    for (int nt = 0; nt < 2; nt++) {
      acc[jc][nt][0] = __expf(acc[jc][nt][0] - m0);
      acc[jc][nt][1] = __expf(acc[jc][nt][1] - m0);
      acc[jc][nt][2] = __expf(acc[jc][nt][2] - m1);
      acc[jc][nt][3] = __expf(acc[jc][nt][3] - m1);
      s0 += acc[jc][nt][0] + acc[jc][nt][1];
      s1 += acc[jc][nt][2] + acc[jc][nt][3];
    }
#pragma unroll
  for (int o = 1; o <= 2; o <<= 1) {
    s0 += __shfl_xor_sync(~0u, s0, o);
    s1 += __shfl_xor_sync(~0u, s1, o);
  }
  if ((lane & 3) == 0) { red[r0][wid] = s0; red[r1][wid] = s1; }
  __syncthreads();
  s0 = 0.f; s1 = 0.f;
#pragma unroll
  for (int q = 0; q < 8; q++) { s0 += red[r0][q]; s1 += red[r1][q]; }
  float inv0 = 1.f / s0, inv1 = 1.f / s1;

  size_t base0 = (((size_t)bh << 10) + (i0 + r0)) << 10;
  size_t base1 = (((size_t)bh << 10) + (i0 + r1)) << 10;
#pragma unroll
  for (int jc = 0; jc < 8; jc++) {
#pragma unroll
    for (int nt = 0; nt < 2; nt++) {
      int col = jc * 128 + nwb + nt * 8 + (lane & 3) * 2;
      B16x2 hp;
      hp.h[0] = __float2bfloat16_rn(acc[jc][nt][0] * inv0);
      hp.h[1] = __float2bfloat16_rn(acc[jc][nt][1] * inv0);
      *(uint32_t*)(g_attn_h + base0 + col) = hp.u;
      hp.h[0] = __float2bfloat16_rn(acc[jc][nt][2] * inv1);
      hp.h[1] = __float2bfloat16_rn(acc[jc][nt][3] * inv1);
      *(uint32_t*)(g_attn_h + base1 + col) = hp.u;
    }
  }
}

// ---------------- Kernel 3: FUSED av + pes (interleaved 1:4) ----------------
#define AV_A (128 * LDSTRIDE)   // 9216
#define AV_V (64 * LDSTRIDE)    // 4608
#define AV_STAGE (AV_A + 2 * AV_V)       // 18432 elements per stage
#define AVP_SMEM_BYTES (2 * AV_STAGE * 2) // 73728 B
__global__ __launch_bounds__(256, 2) void avpes(const float* __restrict__ pe) {
  extern __shared__ __nv_bfloat16 smd[];
  int tid = threadIdx.x;
  int wid = tid >> 5, lane = tid & 31;
  int bq = blockIdx.x / 5, br = blockIdx.x % 5;

  if (br == 0) {
    // =================== AV body (256 blocks) ===================
    int bh = bq >> 3;
    int i0 = (bq & 7) * 128;

    const __nv_bfloat16* vth = g_vth + (size_t)bh * HD * NSEQ;
    const __nv_bfloat16* vtl = g_vtl + (size_t)bh * HD * NSEQ;

    int m_w = (wid >> 1) * 32;
    int n_w = (wid & 1) * 32;
    int r = lane >> 2;
    int g = lane >> 3, rw = lane & 7;

    float c[2][4][4];
#pragma unroll
    for (int mt = 0; mt < 2; mt++)
#pragma unroll
      for (int nt = 0; nt < 4; nt++)
#pragma unroll
        for (int e = 0; e < 4; e++) c[mt][nt][e] = 0.f;

#pragma unroll
    for (int t = 0; t < 4; t++) {
      int idx = tid + 256 * t;
      int rr = idx >> 3, seg = idx & 7;
      size_t gsrc = ((((size_t)bh << 10) + i0 + rr) << 10) + seg * 8;
      cp16(smd + rr * LDSTRIDE + seg * 8, g_attn_h + gsrc);
    }
#pragma unroll
    for (int t = 0; t < 2; t++) {
      int idx = tid + 256 * t;
      int d = idx >> 3, seg = idx & 7;
      int so = AV_A + d * LDSTRIDE + seg * 8;
      cp16(smd + so, vth + (size_t)d * 1024 + seg * 8);
      cp16(smd + AV_V + so, vtl + (size_t)d * 1024 + seg * 8);
    }
    CP_COMMIT();

    for (int ck = 0; ck < 16; ck++) {
      int st = ck & 1;
      if (ck < 15) {
        int sn = st ^ 1;
        __nv_bfloat16* base = smd + sn * AV_STAGE;
#pragma unroll
        for (int t = 0; t < 4; t++) {
          int idx = tid + 256 * t;
          int rr = idx >> 3, seg = idx & 7;
          size_t gsrc = ((((size_t)bh << 10) + i0 + rr) << 10) + (ck + 1) * 64 + seg * 8;
          cp16(base + rr * LDSTRIDE + seg * 8, g_attn_h + gsrc);
        }
#pragma unroll
        for (int t = 0; t < 2; t++) {
          int idx = tid + 256 * t;
          int d = idx >> 3, seg = idx & 7;
          int so = AV_A + d * LDSTRIDE + seg * 8;
          cp16(base + so, vth + (size_t)d * 1024 + (ck + 1) * 64 + seg * 8);
          cp16(base + AV_V + so, vtl + (size_t)d * 1024 + (ck + 1) * 64 + seg * 8);
        }
        CP_COMMIT();
        CP_WAIT1();
      } else {
        CP_WAIT0();
      }
      __syncthreads();
      const __nv_bfloat16* AHs = smd + st * AV_STAGE;
      const __nv_bfloat16* VHs = AHs + AV_A;
      const __nv_bfloat16* VLs = VHs + AV_V;

#pragma unroll
      for (int kb = 0; kb < 64; kb += 16) {
        uint32_t ah[2][4];
#pragma unroll
        for (int mt = 0; mt < 2; mt++)
          ldsm4(ah[mt], AHs + (m_w + mt * 16 + (g & 1) * 8 + rw) * LDSTRIDE + kb + (g >> 1) * 8);
        uint32_t bh4[2][4], bl4[2][4];
#pragma unroll
        for (int p = 0; p < 2; p++) {
          ldsm4(bh4[p], VHs + (n_w + p * 16 + (g >> 1) * 8 + rw) * LDSTRIDE + kb + (g & 1) * 8);
          ldsm4(bl4[p], VLs + (n_w + p * 16 + (g >> 1) * 8 + rw) * LDSTRIDE + kb + (g & 1) * 8);
        }
#pragma unroll
        for (int mt = 0; mt < 2; mt++)
#pragma unroll
          for (int p = 0; p < 2; p++) {
            mma16816(c[mt][2 * p], ah[mt], bh4[p]);
            mma16816(c[mt][2 * p], ah[mt], bl4[p]);
            mma16816(c[mt][2 * p + 1], ah[mt], bh4[p] + 2);
            mma16816(c[mt][2 * p + 1], ah[mt], bl4[p] + 2);
          }
      }
      __syncthreads();
    }

#pragma unroll
    for (int mt = 0; mt < 2; mt++) {
#pragma unroll
      for (int nt = 0; nt < 4; nt++) {
        int row = i0 + m_w + mt * 16 + r;
        int col = n_w + nt * 8 + (lane & 3) * 2;
        float* dst = g_oh + ((size_t)bh * 1024 + row) * 64 + col;
        *(float2*)dst = make_float2(c[mt][nt][0], c[mt][nt][1]);
        *(float2*)(dst + 8 * 64) = make_float2(c[mt][nt][2], c[mt][nt][3]);
      }
    }
  } else {
    // =================== PES body (1024 blocks) ===================
    int i = bq * 4 + (br - 1);
    __nv_bfloat16* AH0 = smd;
    __nv_bfloat16* PH0 = smd + 2 * 32 * PSTRIDE;

    int mw = (wid & 1) * 16;
    int nw = (wid >> 1) * 8;
    int r = lane >> 2, kq = (lane & 3) * 2;

#pragma unroll
    for (int t = 0; t < 2; t++) {
      int idx = tid + 256 * t;
      int row = idx >> 4, seg = idx & 15;
      size_t gsrc = ((size_t)row << 20) + ((size_t)i << 10) + seg * 8;
      cp16(AH0 + row * PSTRIDE + seg * 8, g_attn_h + gsrc);
    }
    CP_COMMIT();
    float4 pv[4];
#pragma unroll
    for (int t = 0; t < 4; t++) {
      int idx = tid + 256 * t;
      int j = idx >> 3, c4 = idx & 7;
      pv[t] = *(const float4*)(pe + (((size_t)i << 10) + j) * 32 + c4 * 4);
    }

    float acc[4] = {};
    for (int kc = 0; kc < 8; kc++) {
      int st = kc & 1;
      if (kc < 7) {
        __nv_bfloat16* AHn = AH0 + (st ^ 1) * 32 * PSTRIDE;
#pragma unroll
        for (int t = 0; t < 2; t++) {
          int idx = tid + 256 * t;
          int row = idx >> 4, seg = idx & 15;
          size_t gsrc = ((size_t)row << 20) + ((size_t)i << 10) + (kc + 1) * 128 + seg * 8;
          cp16(AHn + row * PSTRIDE + seg * 8, g_attn_h + gsrc);
        }
        CP_COMMIT();
      }
      __nv_bfloat16* PHs = PH0 + st * 32 * PSTRIDE;
#pragma unroll
      for (int t = 0; t < 4; t++) {
        int idx = tid + 256 * t;
        int j = idx >> 3, c4 = idx & 7;
        PHs[(c4 * 4 + 0) * PSTRIDE + j] = __float2bfloat16_rn(pv[t].x);
        PHs[(c4 * 4 + 1) * PSTRIDE + j] = __float2bfloat16_rn(pv[t].y);
        PHs[(c4 * 4 + 2) * PSTRIDE + j] = __float2bfloat16_rn(pv[t].z);
        PHs[(c4 * 4 + 3) * PSTRIDE + j] = __float2bfloat16_rn(pv[t].w);
      }
      if (kc < 7) {
#pragma unroll
        for (int t = 0; t < 4; t++) {
          int idx = tid + 256 * t;
          int j = idx >> 3, c4 = idx & 7;
          pv[t] = *(const float4*)(
              pe + (((size_t)i << 10) + (kc + 1) * 128 + j) * 32 + c4 * 4);
        }
      }
      if (kc < 7) CP_WAIT1(); else CP_WAIT0();
      __syncthreads();
      const __nv_bfloat16* AHs = AH0 + st * 32 * PSTRIDE;
#pragma unroll
      for (int kb = 0; kb < 8; kb++) {
        const __nv_bfloat16* p = AHs + (mw + r) * PSTRIDE + kb * 16 + kq;
        uint32_t ah4[4] = {*(const uint32_t*)p,
                           *(const uint32_t*)(p + 8 * PSTRIDE),
                           *(const uint32_t*)(p + 8),
                           *(const uint32_t*)(p + 8 * PSTRIDE + 8)};
        const __nv_bfloat16* pb = PHs + (nw + r) * PSTRIDE + kb * 16 + kq;
        uint32_t bh2[2] = {*(const uint32_t*)pb, *(const uint32_t*)(pb + 8)};
        mma16816(acc, ah4, bh2);
      }
      __syncthreads();
    }
    int c = nw + (lane & 3) * 2;
    int b0 = mw + r, b1 = b0 + 8;
    *(float2*)&g_pes[(((size_t)b0 << 10) + i) * 32 + c] = make_float2(acc[0], acc[1]);
    *(float2*)&g_pes[(((size_t)b1 << 10) + i) * 32 + c] = make_float2(acc[2], acc[3]);
  }
}

// ---------------- Kernel 4: merged = out_head + pe_sum@Wpe + bpe (split) ----
__global__ __launch_bounds__(256) void merge_kernel(
    const float* __restrict__ Wpe, const float* __restrict__ bpe) {
  __shared__ float wpe_s[32 * 64];
  __shared__ float pes_s[32 * 32];
  __shared__ float bpe_s[64];
  int bh = blockIdx.x;
  int n0 = blockIdx.y * 32;
  int tid = threadIdx.x;
#pragma unroll
  for (int r = 0; r < 8; r++) wpe_s[tid + r * 256] = Wpe[tid + r * 256];
  if (tid < 64) bpe_s[tid] = bpe[tid];
  {
    int nl = tid >> 3, cc = tid & 7;
    *(float4*)&pes_s[nl * 32 + cc * 4] =
        *(const float4*)(g_pes + ((size_t)bh * 1024 + n0 + nl) * 32 + cc * 4);
  }
  __syncthreads();
  int nl = tid >> 3;
  int d0 = (tid & 7) * 8;
  int b = bh >> 3, h = bh & 7;
  const float* ohp = g_oh + ((size_t)bh * 1024 + n0 + nl) * 64 + d0;
  float o[8];
#pragma unroll
  for (int dd = 0; dd < 8; dd++) o[dd] = bpe_s[d0 + dd] + ohp[dd];
#pragma unroll 8
  for (int c = 0; c < 32; c++) {
    float pv = pes_s[nl * 32 + c];
#pragma unroll
    for (int dd = 0; dd < 8; dd++) o[dd] += pv * wpe_s[c * 64 + d0 + dd];
  }
  size_t mp = ((size_t)(b * 1024 + n0 + nl)) * 512 + h * 64 + d0;
  B16x8 hh, ll;
#pragma unroll
  for (int dd = 0; dd < 8; dd++) split2(o[dd], hh.h[dd], ll.h[dd]);
  *(uint4*)&g_mh[mp] = hh.u;
  *(uint4*)&g_ml[mp] = ll.u;
}

// ---------------- Kernel 5: out = merged @ Wproj (cp.async pipelined) -------
// M=4096, N=256, K=512. CTA 128m x 64n, grid (32, 4).
#define PRJ_M (128 * LDSTRIDE)
#define PRJ_W (64 * LDSTRIDE)
#define PRJ_STAGE (2 * PRJ_M + 2 * PRJ_W)     // 27648
#define PRJ_SMEM_BYTES (2 * PRJ_STAGE * 2)    // 110592
__global__ __launch_bounds__(256) void proj_mma(float* __restrict__ out) {
  extern __shared__ __nv_bfloat16 sm[];

  int tid = threadIdx.x;
  int wid = tid >> 5, lane = tid & 31;
  int m0 = blockIdx.x * 128;
  int n0 = blockIdx.y * 64;

  int m_w = (wid >> 1) * 32, n_w = (wid & 1) * 32;
  int r = lane >> 2;
  int g = lane >> 3, rw = lane & 7;

  auto stage = [&](int ck, int s) {
    __nv_bfloat16* base = sm + s * PRJ_STAGE;
#pragma unroll
    for (int t = 0; t < 4; t++) {
      int idx = tid + 256 * t;
      int rr = idx >> 3, seg = idx & 7;
      int so = rr * LDSTRIDE + seg * 8;
      size_t gs = (size_t)(m0 + rr) * 512 + ck * 64 + seg * 8;
      cp16(base + so, g_mh + gs);
      cp16(base + PRJ_M + so, g_ml + gs);
    }
#pragma unroll
    for (int t = 0; t < 2; t++) {
      int idx = tid + 256 * t;
      int d = idx >> 3, seg = idx & 7;
      int so = 2 * PRJ_M + d * LDSTRIDE + seg * 8;
      size_t gs = (size_t)(n0 + d) * 512 + ck * 64 + seg * 8;
      cp16(base + so, g_wpth + gs);
      cp16(base + PRJ_W + so, g_wptl + gs);
    }
  };

  float c[2][4][4];
#pragma unroll
  for (int mt = 0; mt < 2; mt++)
#pragma unroll
    for (int nt = 0; nt < 4; nt++)
#pragma unroll
      for (int e = 0; e < 4; e++) c[mt][nt][e] = 0.f;

  stage(0, 0);
  CP_COMMIT();

  for (int ck = 0; ck < 8; ck++) {
    int st = ck & 1;
    if (ck < 7) { stage(ck + 1, st ^ 1); CP_COMMIT(); CP_WAIT1(); }
    else CP_WAIT0();
    __syncthreads();
    const __nv_bfloat16* MH = sm + st * PRJ_STAGE;
    const __nv_bfloat16* ML = MH + PRJ_M;
    const __nv_bfloat16* WH = ML + PRJ_M;
    const __nv_bfloat16* WL = WH + PRJ_W;
#pragma unroll
    for (int kb = 0; kb < 64; kb += 16) {
      uint32_t ah[2][4], al[2][4];
#pragma unroll
      for (int mt = 0; mt < 2; mt++) {
        ldsm4(ah[mt], MH + (m_w + mt * 16 + (g & 1) * 8 + rw) * LDSTRIDE + kb + (g >> 1) * 8);
        ldsm4(al[mt], ML + (m_w + mt * 16 + (g & 1) * 8 + rw) * LDSTRIDE + kb + (g >> 1) * 8);
      }
      uint32_t bh4[2][4], bl4[2][4];
#pragma unroll
      for (int p = 0; p < 2; p++) {
        ldsm4(bh4[p], WH + (n_w + p * 16 + (g >> 1) * 8 + rw) * LDSTRIDE + kb + (g & 1) * 8);
        ldsm4(bl4[p], WL + (n_w + p * 16 + (g >> 1) * 8 + rw) * LDSTRIDE + kb + (g & 1) * 8);
      }
#pragma unroll
      for (int mt = 0; mt < 2; mt++)
#pragma unroll
        for (int p = 0; p < 2; p++) {
          mma16816(c[mt][2 * p], ah[mt], bh4[p]);
          mma16816(c[mt][2 * p], ah[mt], bl4[p]);
          mma16816(c[mt][2 * p], al[mt], bh4[p]);
          mma16816(c[mt][2 * p + 1], ah[mt], bh4[p] + 2);
          mma16816(c[mt][2 * p + 1], ah[mt], bl4[p] + 2);
          mma16816(c[mt][2 * p + 1], al[mt], bh4[p] + 2);
        }
    }
    __syncthreads();
  }

#pragma unroll
  for (int mt = 0; mt < 2; mt++) {
#pragma unroll
    for (int nt = 0; nt < 4; nt++) {
      int row = m0 + m_w + mt * 16 + r;
      int col = n0 + n_w + nt * 8 + (lane & 3) * 2;
      float* dst = out + (size_t)row * 256 + col;
      *(float2*)dst = make_float2(c[mt][nt][0], c[mt][nt][1]);
      *(float2*)(dst + 8 * 256) = make_float2(c[mt][nt][2], c[mt][nt][3]);
    }
  }
}

// ---------------- launch -----------------------------------------------------
extern "C" void kernel_launch(void* const* d_in, const int* in_sizes, int n_in,
                              void* d_out, int out_size) {
  const float* x     = (const float*)d_in[0];
  const float* pe    = (const float*)d_in[1];
  const float* Wq    = (const float*)d_in[2];
  const float* Wk    = (const float*)d_in[3];
  const float* Wv    = (const float*)d_in[4];
  const float* bv    = (const float*)d_in[5];
  const float* Wpe   = (const float*)d_in[6];
  const float* bpe   = (const float*)d_in[7];
  const float* Wproj = (const float*)d_in[8];
  float* out = (float*)d_out;

  cudaFuncSetAttribute(qkv_mma, cudaFuncAttributeMaxDynamicSharedMemorySize,
                       QKV_SMEM_BYTES);
  cudaFuncSetAttribute(scoresm, cudaFuncAttributeMaxDynamicSharedMemorySize,
                       SM_SMEM_BYTES);
  cudaFuncSetAttribute(avpes, cudaFuncAttributeMaxDynamicSharedMemorySize,
                       AVP_SMEM_BYTES);
  cudaFuncSetAttribute(proj_mma, cudaFuncAttributeMaxDynamicSharedMemorySize,
                       PRJ_SMEM_BYTES);

  prep_all<<<1536, 256>>>(x, Wq, Wk, Wv, Wproj);
  qkv_mma<<<dim3(32, 24), 256, QKV_SMEM_BYTES>>>(bv);
  scoresm<<<dim3(64, 32), 256, SM_SMEM_BYTES>>>();
  avpes<<<1280, 256, AVP_SMEM_BYTES>>>(pe);
  merge_kernel<<<dim3(32, 32), 256>>>(Wpe, bpe);
  proj_mma<<<dim3(32, 4), 256, PRJ_SMEM_BYTES>>>(out);
}

// round 15
// speedup vs baseline: 1.0612x; 1.0612x over previous
#include <cuda_runtime.h>
#include <cuda_bf16.h>
#include <cstdint>

#define NSEQ 1024
#define DIM  256
#define HEADS 8
#define EDIM 512
#define HD   64
#define PEC  32
#define BH   32           // B*HEADS
#define ROWS 4096         // B*N

// ---------------- scratch (device globals; no runtime allocation) ----------
__device__ __nv_bfloat16 g_xh[ROWS * DIM], g_xl[ROWS * DIM];
__device__ __nv_bfloat16 g_wth[1536 * 256], g_wtl[1536 * 256];   // [n][k]
__device__ __nv_bfloat16 g_wpth[256 * 512], g_wptl[256 * 512];   // [n][k]
__device__ __nv_bfloat16 g_qh[BH * NSEQ * HD];
__device__ __nv_bfloat16 g_ql[BH * NSEQ * HD];
__device__ __nv_bfloat16 g_kh[BH * NSEQ * HD];
__device__ __nv_bfloat16 g_kl[BH * NSEQ * HD];
__device__ __nv_bfloat16 g_vth[BH * HD * NSEQ];   // transposed: [bh][d][n]
__device__ __nv_bfloat16 g_vtl[BH * HD * NSEQ];
__device__ __nv_bfloat16 g_attn_h[(size_t)BH * NSEQ * NSEQ];  // 64 MB
__device__ float g_oh[BH * NSEQ * HD];
__device__ float g_pes[BH * NSEQ * PEC];
__device__ __nv_bfloat16 g_mh[ROWS * EDIM], g_ml[ROWS * EDIM];

union B16x8 { __nv_bfloat16 h[8]; uint4 u; };
union B16x4 { __nv_bfloat16 h[4]; uint2 u; };
union B16x2 { __nv_bfloat16 h[2]; uint32_t u; };

__device__ __forceinline__ void split2(float x, __nv_bfloat16& h, __nv_bfloat16& l) {
  h = __float2bfloat16_rn(x);
  l = __float2bfloat16_rn(x - __bfloat162float(h));
}

// m16n8k16 bf16 mma with fp32 accumulate (row.col)
__device__ __forceinline__ void mma16816(float* c, const uint32_t* a,
                                         const uint32_t* b) {
  asm volatile(
      "mma.sync.aligned.m16n8k16.row.col.f32.bf16.bf16.f32 "
      "{%0,%1,%2,%3}, {%4,%5,%6,%7}, {%8,%9}, {%0,%1,%2,%3};"
      : "+f"(c[0]), "+f"(c[1]), "+f"(c[2]), "+f"(c[3])
      : "r"(a[0]), "r"(a[1]), "r"(a[2]), "r"(a[3]), "r"(b[0]), "r"(b[1]));
}

// ldmatrix x4: 4 8x8 b16 tiles; lane group g=lane>>3 supplies address of tile g
__device__ __forceinline__ void ldsm4(uint32_t* d, const __nv_bfloat16* p) {
  uint32_t a = (uint32_t)__cvta_generic_to_shared(p);
  asm volatile("ldmatrix.sync.aligned.m8n8.x4.shared.b16 {%0,%1,%2,%3}, [%4];"
               : "=r"(d[0]), "=r"(d[1]), "=r"(d[2]), "=r"(d[3]) : "r"(a));
}

// 16B async copy gmem -> smem
__device__ __forceinline__ void cp16(__nv_bfloat16* smem_ptr, const __nv_bfloat16* gptr) {
  uint32_t s = (uint32_t)__cvta_generic_to_shared(smem_ptr);
  asm volatile("cp.async.cg.shared.global [%0], [%1], 16;" :: "r"(s), "l"(gptr));
}
#define CP_COMMIT() asm volatile("cp.async.commit_group;" ::: "memory")
#define CP_WAIT1()  asm volatile("cp.async.wait_group 1;" ::: "memory")
#define CP_WAIT0()  asm volatile("cp.async.wait_group 0;" ::: "memory")

#define LDSTRIDE 72   // bf16 units per SMEM row (64 data + 8 pad)
#define PSTRIDE 136   // bf16 units per SMEM row (128 data + 8 pad)
#define GEMM_SMEM_BYTES ((2 * 128 + 2 * 64) * LDSTRIDE * 2)   // 55296

// ---------------- prep: split x + transpose/split weights (fused) -----------
__global__ __launch_bounds__(256) void prep_all(
    const float* __restrict__ x, const float* __restrict__ Wq,
    const float* __restrict__ Wk, const float* __restrict__ Wv,
    const float* __restrict__ Wproj) {
  if (blockIdx.x < 1024) {
    int idx = (blockIdx.x * 256 + threadIdx.x) * 4;
    float4 v = *(const float4*)(x + idx);
    B16x4 hh, ll;
    split2(v.x, hh.h[0], ll.h[0]); split2(v.y, hh.h[1], ll.h[1]);
    split2(v.z, hh.h[2], ll.h[2]); split2(v.w, hh.h[3], ll.h[3]);
    *(uint2*)&g_xh[idx] = hh.u;
    *(uint2*)&g_xl[idx] = ll.u;
    return;
  }
  int id = (blockIdx.x - 1024) * 256 + threadIdx.x;
  if (id < 98304) {                 // WT: 1536 n x 64 k-groups
    int n = id >> 6, k0 = (id & 63) * 4;
    int sel = n >> 9, col = n & 511;
    const float* W = (sel == 0) ? Wq : (sel == 1) ? Wk : Wv;
#pragma unroll
    for (int q = 0; q < 4; q++) {
      float v = W[(k0 + q) * 512 + col];
      split2(v, g_wth[n * 256 + k0 + q], g_wtl[n * 256 + k0 + q]);
    }
  } else {                          // WprojT: 256 n x 128 k-groups
    int id2 = id - 98304;
    int n = id2 >> 7, k0 = (id2 & 127) * 4;
#pragma unroll
    for (int q = 0; q < 4; q++) {
      float v = Wproj[(k0 + q) * 256 + n];
      split2(v, g_wpth[n * 512 + k0 + q], g_wptl[n * 512 + k0 + q]);
    }
  }
}

// ---------------- Kernel 1: QKV projection via mma.sync ---------------------
// M=4096, N=1536, K=256. CTA 128m x 64n, grid (32, 24). 8 warps: 4m x 2n.
__global__ __launch_bounds__(256) void qkv_mma(const float* __restrict__ bv) {
  extern __shared__ __nv_bfloat16 sm[];
  __nv_bfloat16* XH = sm;
  __nv_bfloat16* XL = XH + 128 * LDSTRIDE;
  __nv_bfloat16* WH = XL + 128 * LDSTRIDE;
  __nv_bfloat16* WL = WH + 64 * LDSTRIDE;

  int tid = threadIdx.x;
  int wid = tid >> 5, lane = tid & 31;
  int m0 = blockIdx.x * 128;
  int n0 = blockIdx.y * 64;
  int sel = n0 / 512;
  int e0 = n0 % 512;
  int h = e0 / 64;

  int m_w = (wid >> 1) * 32, n_w = (wid & 1) * 32;
  int r = lane >> 2;
  int g = lane >> 3, rw = lane & 7;

  float c[2][4][4];
#pragma unroll
  for (int mt = 0; mt < 2; mt++)
#pragma unroll
    for (int nt = 0; nt < 4; nt++)
#pragma unroll
      for (int e = 0; e < 4; e++) c[mt][nt][e] = 0.f;

  for (int ck = 0; ck < 4; ck++) {
    if (ck) __syncthreads();
#pragma unroll
    for (int t = 0; t < 4; t++) {
      int idx = tid + 256 * t;
      int rr = idx >> 3, seg = idx & 7;
      int so = rr * LDSTRIDE + seg * 8;
      size_t gs = (size_t)(m0 + rr) * 256 + ck * 64 + seg * 8;
      *(uint4*)(XH + so) = *(const uint4*)(g_xh + gs);
      *(uint4*)(XL + so) = *(const uint4*)(g_xl + gs);
    }
#pragma unroll
    for (int t = 0; t < 2; t++) {
      int idx = tid + 256 * t;
      int d = idx >> 3, seg = idx & 7;
      int so = d * LDSTRIDE + seg * 8;
      size_t gs = (size_t)(n0 + d) * 256 + ck * 64 + seg * 8;
      *(uint4*)(WH + so) = *(const uint4*)(g_wth + gs);
      *(uint4*)(WL + so) = *(const uint4*)(g_wtl + gs);
    }
    __syncthreads();
#pragma unroll
    for (int kb = 0; kb < 64; kb += 16) {
      uint32_t ah[2][4], al[2][4];
#pragma unroll
      for (int mt = 0; mt < 2; mt++) {
        ldsm4(ah[mt], XH + (m_w + mt * 16 + (g & 1) * 8 + rw) * LDSTRIDE + kb + (g >> 1) * 8);
        ldsm4(al[mt], XL + (m_w + mt * 16 + (g & 1) * 8 + rw) * LDSTRIDE + kb + (g >> 1) * 8);
      }
      uint32_t bh4[2][4], bl4[2][4];
#pragma unroll
      for (int p = 0; p < 2; p++) {
        ldsm4(bh4[p], WH + (n_w + p * 16 + (g >> 1) * 8 + rw) * LDSTRIDE + kb + (g & 1) * 8);
        ldsm4(bl4[p], WL + (n_w + p * 16 + (g >> 1) * 8 + rw) * LDSTRIDE + kb + (g & 1) * 8);
      }
#pragma unroll
      for (int mt = 0; mt < 2; mt++)
#pragma unroll
        for (int p = 0; p < 2; p++) {
          mma16816(c[mt][2 * p], ah[mt], bh4[p]);
          mma16816(c[mt][2 * p], ah[mt], bl4[p]);
          mma16816(c[mt][2 * p], al[mt], bh4[p]);
          mma16816(c[mt][2 * p + 1], ah[mt], bh4[p] + 2);
          mma16816(c[mt][2 * p + 1], ah[mt], bl4[p] + 2);
          mma16816(c[mt][2 * p + 1], al[mt], bh4[p] + 2);
        }
    }
  }

#pragma unroll
  for (int mt = 0; mt < 2; mt++) {
#pragma unroll
    for (int nt = 0; nt < 4; nt++) {
      int colw = n_w + nt * 8 + (lane & 3) * 2;   // 0..62, even
      int d = colw;                                // channel within head
      int e = e0 + colw;
#pragma unroll
      for (int half = 0; half < 2; half++) {
        int row = m0 + m_w + mt * 16 + r + half * 8;
        float v0 = c[mt][nt][half * 2 + 0];
        float v1 = c[mt][nt][half * 2 + 1];
        int b = row >> 10, n = row & 1023;
        int bh = b * 8 + h;
        if (sel == 0) {
          v0 *= 0.125f; v1 *= 0.125f;
          B16x2 hp, lp;
          split2(v0, hp.h[0], lp.h[0]); split2(v1, hp.h[1], lp.h[1]);
          size_t idx = ((size_t)bh * 1024 + n) * 64 + d;
          *(uint32_t*)&g_qh[idx] = hp.u;
          *(uint32_t*)&g_ql[idx] = lp.u;
        } else if (sel == 1) {
          B16x2 hp, lp;
          split2(v0, hp.h[0], lp.h[0]); split2(v1, hp.h[1], lp.h[1]);
          size_t idx = ((size_t)bh * 1024 + n) * 64 + d;
          *(uint32_t*)&g_kh[idx] = hp.u;
          *(uint32_t*)&g_kl[idx] = lp.u;
        } else {
          v0 += bv[e]; v1 += bv[e + 1];
          __nv_bfloat16 hh, ll;
          split2(v0, hh, ll);
          size_t i0v = ((size_t)bh * 64 + d) * 1024 + n;
          g_vth[i0v] = hh; g_vtl[i0v] = ll;
          split2(v1, hh, ll);
          size_t i1v = ((size_t)bh * 64 + d + 1) * 1024 + n;
          g_vth[i1v] = hh; g_vtl[i1v] = ll;
        }
      }
    }
  }
}

// ---------------- Kernel 2: fused scores + softmax (16-row CTAs) ------------
#define KSTAGE (128 * LDSTRIDE)     // 9216 elements per K stage
#define SM_SMEM_BYTES ((2 * 16 * LDSTRIDE + 2 * KSTAGE) * 2)   // 41472 B
__global__ __launch_bounds__(256, 2) void scoresm() {
  extern __shared__ __nv_bfloat16 smd[];
  __nv_bfloat16* QH = smd;
  __nv_bfloat16* QL = QH + 16 * LDSTRIDE;
  __nv_bfloat16* KHb = QL + 16 * LDSTRIDE;   // 2 stages of KSTAGE
  __shared__ float red[16][8];

  int tid = threadIdx.x;
  int wid = tid >> 5, lane = tid & 31;
  int bh = blockIdx.y;
  int i0 = blockIdx.x * 16;

  const __nv_bfloat16* qh = g_qh + (size_t)bh * NSEQ * HD;
  const __nv_bfloat16* ql = g_ql + (size_t)bh * NSEQ * HD;
  const __nv_bfloat16* kh = g_kh + (size_t)bh * NSEQ * HD;

  if (tid < 128) {
    int r = tid >> 3, seg = tid & 7;
    int so = r * LDSTRIDE + seg * 8;
    *(uint4*)(QH + so) = *(const uint4*)(qh + (i0 + r) * 64 + seg * 8);
    *(uint4*)(QL + so) = *(const uint4*)(ql + (i0 + r) * 64 + seg * 8);
  }
#pragma unroll
  for (int t = 0; t < 4; t++) {
    int idx = tid + 256 * t;
    int rr = idx >> 3, seg = idx & 7;
    cp16(KHb + rr * LDSTRIDE + seg * 8, kh + rr * 64 + seg * 8);
  }
  CP_COMMIT();

  int nwb = wid * 16;
  int r = lane >> 2;
  int g = lane >> 3, rw = lane & 7;

  uint32_t ah[4][4], al[4][4];
  float acc[8][2][4];
#pragma unroll
  for (int jc = 0; jc < 8; jc++)
#pragma unroll
    for (int nt = 0; nt < 2; nt++)
#pragma unroll
      for (int e = 0; e < 4; e++) acc[jc][nt][e] = 0.f;

#pragma unroll
  for (int jc = 0; jc < 8; jc++) {
    int st = jc & 1;
    if (jc < 7) {
      int sn = st ^ 1;
#pragma unroll
      for (int t = 0; t < 4; t++) {
        int idx = tid + 256 * t;
        int rr = idx >> 3, seg = idx & 7;
        cp16(KHb + sn * KSTAGE + rr * LDSTRIDE + seg * 8,
             kh + ((jc + 1) * 128 + rr) * 64 + seg * 8);
      }
      CP_COMMIT();
      CP_WAIT1();
    } else {
      CP_WAIT0();
    }
    __syncthreads();
    const __nv_bfloat16* KH = KHb + st * KSTAGE;
    if (jc == 0) {
#pragma unroll
      for (int kb = 0; kb < 4; kb++) {
        ldsm4(ah[kb], QH + ((g & 1) * 8 + rw) * LDSTRIDE + kb * 16 + (g >> 1) * 8);
        ldsm4(al[kb], QL + ((g & 1) * 8 + rw) * LDSTRIDE + kb * 16 + (g >> 1) * 8);
      }
    }
#pragma unroll
    for (int kb = 0; kb < 4; kb++) {
      uint32_t b4[4];
      ldsm4(b4, KH + (nwb + (g >> 1) * 8 + rw) * LDSTRIDE + kb * 16 + (g & 1) * 8);
      mma16816(acc[jc][0], ah[kb], b4);
      mma16816(acc[jc][0], al[kb], b4);
      mma16816(acc[jc][1], ah[kb], b4 + 2);
      mma16816(acc[jc][1], al[kb], b4 + 2);
    }
    __syncthreads();
  }

  int r0 = r, r1 = r0 + 8;
  float m0 = -1e30f, m1 = -1e30f;
#pragma unroll
  for (int jc = 0; jc < 8; jc++)
#pragma unroll
    for (int nt = 0; nt < 2; nt++) {
      m0 = fmaxf(m0, fmaxf(acc[jc][nt][0], acc[jc][nt][1]));
      m1 = fmaxf(m1, fmaxf(acc[jc][nt][2], acc[jc][nt][3]));
    }
#pragma unroll
  for (int o = 1; o <= 2; o <<= 1) {
    m0 = fmaxf(m0, __shfl_xor_sync(~0u, m0, o));
    m1 = fmaxf(m1, __shfl_xor_sync(~0u, m1, o));
  }
  if ((lane & 3) == 0) { red[r0][wid] = m0; red[r1][wid] = m1; }
  __syncthreads();
#pragma unroll
  for (int q = 0; q < 8; q++) {
    m0 = fmaxf(m0, red[r0][q]);
    m1 = fmaxf(m1, red[r1][q]);
  }
  __syncthreads();

  float s0 = 0.f, s1 = 0.f;
#pragma unroll
  for (int jc = 0; jc < 8; jc++)
#pragma unroll
    for (int nt = 0; nt < 2; nt++) {
      acc[jc][nt][0] = __expf(acc[jc][nt][0] - m0);
      acc[jc][nt][1] = __expf(acc[jc][nt][1] - m0);
      acc[jc][nt][2] = __expf(acc[jc][nt][2] - m1);
      acc[jc][nt][3] = __expf(acc[jc][nt][3] - m1);
      s0 += acc[jc][nt][0] + acc[jc][nt][1];
      s1 += acc[jc][nt][2] + acc[jc][nt][3];
    }
#pragma unroll
  for (int o = 1; o <= 2; o <<= 1) {
    s0 += __shfl_xor_sync(~0u, s0, o);
    s1 += __shfl_xor_sync(~0u, s1, o);
  }
  if ((lane & 3) == 0) { red[r0][wid] = s0; red[r1][wid] = s1; }
  __syncthreads();
  s0 = 0.f; s1 = 0.f;
#pragma unroll
  for (int q = 0; q < 8; q++) { s0 += red[r0][q]; s1 += red[r1][q]; }
  float inv0 = 1.f / s0, inv1 = 1.f / s1;

  size_t base0 = (((size_t)bh << 10) + (i0 + r0)) << 10;
  size_t base1 = (((size_t)bh << 10) + (i0 + r1)) << 10;
#pragma unroll
  for (int jc = 0; jc < 8; jc++) {
#pragma unroll
    for (int nt = 0; nt < 2; nt++) {
      int col = jc * 128 + nwb + nt * 8 + (lane & 3) * 2;
      B16x2 hp;
      hp.h[0] = __float2bfloat16_rn(acc[jc][nt][0] * inv0);
      hp.h[1] = __float2bfloat16_rn(acc[jc][nt][1] * inv0);
      *(uint32_t*)(g_attn_h + base0 + col) = hp.u;
      hp.h[0] = __float2bfloat16_rn(acc[jc][nt][2] * inv1);
      hp.h[1] = __float2bfloat16_rn(acc[jc][nt][3] * inv1);
      *(uint32_t*)(g_attn_h + base1 + col) = hp.u;
    }
  }
}

// ---------------- Kernel 3: FUSED av + pes (contiguous blocks) --------------
#define AV_A (128 * LDSTRIDE)   // 9216
#define AV_V (64 * LDSTRIDE)    // 4608
#define AV_STAGE (AV_A + 2 * AV_V)       // 18432 elements per stage
#define AVP_SMEM_BYTES (2 * AV_STAGE * 2) // 73728 B
__global__ __launch_bounds__(256, 2) void avpes(const float* __restrict__ pe) {
  extern __shared__ __nv_bfloat16 smd[];
  int tid = threadIdx.x;
  int wid = tid >> 5, lane = tid & 31;

  if (blockIdx.x < 256) {
    // =================== AV body ===================
    int bh = blockIdx.x >> 3;
    int i0 = (blockIdx.x & 7) * 128;

    const __nv_bfloat16* vth = g_vth + (size_t)bh * HD * NSEQ;
    const __nv_bfloat16* vtl = g_vtl + (size_t)bh * HD * NSEQ;

    int m_w = (wid >> 1) * 32;
    int n_w = (wid & 1) * 32;
    int r = lane >> 2;
    int g = lane >> 3, rw = lane & 7;

    float c[2][4][4];
#pragma unroll
    for (int mt = 0; mt < 2; mt++)
#pragma unroll
      for (int nt = 0; nt < 4; nt++)
#pragma unroll
        for (int e = 0; e < 4; e++) c[mt][nt][e] = 0.f;

#pragma unroll
    for (int t = 0; t < 4; t++) {
      int idx = tid + 256 * t;
      int rr = idx >> 3, seg = idx & 7;
      size_t gsrc = ((((size_t)bh << 10) + i0 + rr) << 10) + seg * 8;
      cp16(smd + rr * LDSTRIDE + seg * 8, g_attn_h + gsrc);
    }
#pragma unroll
    for (int t = 0; t < 2; t++) {
      int idx = tid + 256 * t;
      int d = idx >> 3, seg = idx & 7;
      int so = AV_A + d * LDSTRIDE + seg * 8;
      cp16(smd + so, vth + (size_t)d * 1024 + seg * 8);
      cp16(smd + AV_V + so, vtl + (size_t)d * 1024 + seg * 8);
    }
    CP_COMMIT();

    for (int ck = 0; ck < 16; ck++) {
      int st = ck & 1;
      if (ck < 15) {
        int sn = st ^ 1;
        __nv_bfloat16* base = smd + sn * AV_STAGE;
#pragma unroll
        for (int t = 0; t < 4; t++) {
          int idx = tid + 256 * t;
          int rr = idx >> 3, seg = idx & 7;
          size_t gsrc = ((((size_t)bh << 10) + i0 + rr) << 10) + (ck + 1) * 64 + seg * 8;
          cp16(base + rr * LDSTRIDE + seg * 8, g_attn_h + gsrc);
        }
#pragma unroll
        for (int t = 0; t < 2; t++) {
          int idx = tid + 256 * t;
          int d = idx >> 3, seg = idx & 7;
          int so = AV_A + d * LDSTRIDE + seg * 8;
          cp16(base + so, vth + (size_t)d * 1024 + (ck + 1) * 64 + seg * 8);
          cp16(base + AV_V + so, vtl + (size_t)d * 1024 + (ck + 1) * 64 + seg * 8);
        }
        CP_COMMIT();
        CP_WAIT1();
      } else {
        CP_WAIT0();
      }
      __syncthreads();
      const __nv_bfloat16* AHs = smd + st * AV_STAGE;
      const __nv_bfloat16* VHs = AHs + AV_A;
      const __nv_bfloat16* VLs = VHs + AV_V;

#pragma unroll
      for (int kb = 0; kb < 64; kb += 16) {
        uint32_t ah[2][4];
#pragma unroll
        for (int mt = 0; mt < 2; mt++)
          ldsm4(ah[mt], AHs + (m_w + mt * 16 + (g & 1) * 8 + rw) * LDSTRIDE + kb + (g >> 1) * 8);
        uint32_t bh4[2][4], bl4[2][4];
#pragma unroll
        for (int p = 0; p < 2; p++) {
          ldsm4(bh4[p], VHs + (n_w + p * 16 + (g >> 1) * 8 + rw) * LDSTRIDE + kb + (g & 1) * 8);
          ldsm4(bl4[p], VLs + (n_w + p * 16 + (g >> 1) * 8 + rw) * LDSTRIDE + kb + (g & 1) * 8);
        }
#pragma unroll
        for (int mt = 0; mt < 2; mt++)
#pragma unroll
          for (int p = 0; p < 2; p++) {
            mma16816(c[mt][2 * p], ah[mt], bh4[p]);
            mma16816(c[mt][2 * p], ah[mt], bl4[p]);
            mma16816(c[mt][2 * p + 1], ah[mt], bh4[p] + 2);
            mma16816(c[mt][2 * p + 1], ah[mt], bl4[p] + 2);
          }
      }
      __syncthreads();
    }

#pragma unroll
    for (int mt = 0; mt < 2; mt++) {
#pragma unroll
      for (int nt = 0; nt < 4; nt++) {
        int row = i0 + m_w + mt * 16 + r;
        int col = n_w + nt * 8 + (lane & 3) * 2;
        float* dst = g_oh + ((size_t)bh * 1024 + row) * 64 + col;
        *(float2*)dst = make_float2(c[mt][nt][0], c[mt][nt][1]);
        *(float2*)(dst + 8 * 64) = make_float2(c[mt][nt][2], c[mt][nt][3]);
      }
    }
  } else {
    // =================== PES body ===================
    int i = blockIdx.x - 256;
    __nv_bfloat16* AH0 = smd;
    __nv_bfloat16* PH0 = smd + 2 * 32 * PSTRIDE;

    int mw = (wid & 1) * 16;
    int nw = (wid >> 1) * 8;
    int r = lane >> 2, kq = (lane & 3) * 2;

#pragma unroll
    for (int t = 0; t < 2; t++) {
      int idx = tid + 256 * t;
      int row = idx >> 4, seg = idx & 15;
      size_t gsrc = ((size_t)row << 20) + ((size_t)i << 10) + seg * 8;
      cp16(AH0 + row * PSTRIDE + seg * 8, g_attn_h + gsrc);
    }
    CP_COMMIT();
    float4 pv[4];
#pragma unroll
    for (int t = 0; t < 4; t++) {
      int idx = tid + 256 * t;
      int j = idx >> 3, c4 = idx & 7;
      pv[t] = *(const float4*)(pe + (((size_t)i << 10) + j) * 32 + c4 * 4);
    }

    float acc[4] = {};
    for (int kc = 0; kc < 8; kc++) {
      int st = kc & 1;
      if (kc < 7) {
        __nv_bfloat16* AHn = AH0 + (st ^ 1) * 32 * PSTRIDE;
#pragma unroll
        for (int t = 0; t < 2; t++) {
          int idx = tid + 256 * t;
          int row = idx >> 4, seg = idx & 15;
          size_t gsrc = ((size_t)row << 20) + ((size_t)i << 10) + (kc + 1) * 128 + seg * 8;
          cp16(AHn + row * PSTRIDE + seg * 8, g_attn_h + gsrc);
        }
        CP_COMMIT();
      }
      __nv_bfloat16* PHs = PH0 + st * 32 * PSTRIDE;
#pragma unroll
      for (int t = 0; t < 4; t++) {
        int idx = tid + 256 * t;
        int j = idx >> 3, c4 = idx & 7;
        PHs[(c4 * 4 + 0) * PSTRIDE + j] = __float2bfloat16_rn(pv[t].x);
        PHs[(c4 * 4 + 1) * PSTRIDE + j] = __float2bfloat16_rn(pv[t].y);
        PHs[(c4 * 4 + 2) * PSTRIDE + j] = __float2bfloat16_rn(pv[t].z);
        PHs[(c4 * 4 + 3) * PSTRIDE + j] = __float2bfloat16_rn(pv[t].w);
      }
      if (kc < 7) {
#pragma unroll
        for (int t = 0; t < 4; t++) {
          int idx = tid + 256 * t;
          int j = idx >> 3, c4 = idx & 7;
          pv[t] = *(const float4*)(
              pe + (((size_t)i << 10) + (kc + 1) * 128 + j) * 32 + c4 * 4);
        }
      }
      if (kc < 7) CP_WAIT1(); else CP_WAIT0();
      __syncthreads();
      const __nv_bfloat16* AHs = AH0 + st * 32 * PSTRIDE;
#pragma unroll
      for (int kb = 0; kb < 8; kb++) {
        const __nv_bfloat16* p = AHs + (mw + r) * PSTRIDE + kb * 16 + kq;
        uint32_t ah4[4] = {*(const uint32_t*)p,
                           *(const uint32_t*)(p + 8 * PSTRIDE),
                           *(const uint32_t*)(p + 8),
                           *(const uint32_t*)(p + 8 * PSTRIDE + 8)};
        const __nv_bfloat16* pb = PHs + (nw + r) * PSTRIDE + kb * 16 + kq;
        uint32_t bh2[2] = {*(const uint32_t*)pb, *(const uint32_t*)(pb + 8)};
        mma16816(acc, ah4, bh2);
      }
      __syncthreads();
    }
    int c = nw + (lane & 3) * 2;
    int b0 = mw + r, b1 = b0 + 8;
    *(float2*)&g_pes[(((size_t)b0 << 10) + i) * 32 + c] = make_float2(acc[0], acc[1]);
    *(float2*)&g_pes[(((size_t)b1 << 10) + i) * 32 + c] = make_float2(acc[2], acc[3]);
  }
}

// ---------------- Kernel 4: merged = out_head + pe_sum@Wpe + bpe (split) ----
__global__ __launch_bounds__(256) void merge_kernel(
    const float* __restrict__ Wpe, const float* __restrict__ bpe) {
  __shared__ float wpe_s[32 * 64];
  __shared__ float pes_s[32 * 32];
  __shared__ float bpe_s[64];
  int bh = blockIdx.x;
  int n0 = blockIdx.y * 32;
  int tid = threadIdx.x;
#pragma unroll
  for (int r = 0; r < 8; r++) wpe_s[tid + r * 256] = Wpe[tid + r * 256];
  if (tid < 64) bpe_s[tid] = bpe[tid];
  {
    int nl = tid >> 3, cc = tid & 7;
    *(float4*)&pes_s[nl * 32 + cc * 4] =
        *(const float4*)(g_pes + ((size_t)bh * 1024 + n0 + nl) * 32 + cc * 4);
  }
  __syncthreads();
  int nl = tid >> 3;
  int d0 = (tid & 7) * 8;
  int b = bh >> 3, h = bh & 7;
  const float* ohp = g_oh + ((size_t)bh * 1024 + n0 + nl) * 64 + d0;
  float o[8];
#pragma unroll
  for (int dd = 0; dd < 8; dd++) o[dd] = bpe_s[d0 + dd] + ohp[dd];
#pragma unroll 8
  for (int c = 0; c < 32; c++) {
    float pv = pes_s[nl * 32 + c];
#pragma unroll
    for (int dd = 0; dd < 8; dd++) o[dd] += pv * wpe_s[c * 64 + d0 + dd];
  }
  size_t mp = ((size_t)(b * 1024 + n0 + nl)) * 512 + h * 64 + d0;
  B16x8 hh, ll;
#pragma unroll
  for (int dd = 0; dd < 8; dd++) split2(o[dd], hh.h[dd], ll.h[dd]);
  *(uint4*)&g_mh[mp] = hh.u;
  *(uint4*)&g_ml[mp] = ll.u;
}

// ---------------- Kernel 5: out = merged @ Wproj (cp.async pipelined) -------
// M=4096, N=256, K=512. CTA 128m x 64n, grid (32, 4). Single wave.
#define PRJ_M (128 * LDSTRIDE)
#define PRJ_W (64 * LDSTRIDE)
#define PRJ_STAGE (2 * PRJ_M + 2 * PRJ_W)     // 27648
#define PRJ_SMEM_BYTES (2 * PRJ_STAGE * 2)    // 110592
__global__ __launch_bounds__(256) void proj_mma(float* __restrict__ out) {
  extern __shared__ __nv_bfloat16 sm[];

  int tid = threadIdx.x;
  int wid = tid >> 5, lane = tid & 31;
  int m0 = blockIdx.x * 128;
  int n0 = blockIdx.y * 64;

  int m_w = (wid >> 1) * 32, n_w = (wid & 1) * 32;
  int r = lane >> 2;
  int g = lane >> 3, rw = lane & 7;

  auto stage = [&](int ck, int s) {
    __nv_bfloat16* base = sm + s * PRJ_STAGE;
#pragma unroll
    for (int t = 0; t < 4; t++) {
      int idx = tid + 256 * t;
      int rr = idx >> 3, seg = idx & 7;
      int so = rr * LDSTRIDE + seg * 8;
      size_t gs = (size_t)(m0 + rr) * 512 + ck * 64 + seg * 8;
      cp16(base + so, g_mh + gs);
      cp16(base + PRJ_M + so, g_ml + gs);
    }
#pragma unroll
    for (int t = 0; t < 2; t++) {
      int idx = tid + 256 * t;
      int d = idx >> 3, seg = idx & 7;
      int so = 2 * PRJ_M + d * LDSTRIDE + seg * 8;
      size_t gs = (size_t)(n0 + d) * 512 + ck * 64 + seg * 8;
      cp16(base + so, g_wpth + gs);
      cp16(base + PRJ_W + so, g_wptl + gs);
    }
  };

  float c[2][4][4];
#pragma unroll
  for (int mt = 0; mt < 2; mt++)
#pragma unroll
    for (int nt = 0; nt < 4; nt++)
#pragma unroll
      for (int e = 0; e < 4; e++) c[mt][nt][e] = 0.f;

  stage(0, 0);
  CP_COMMIT();

  for (int ck = 0; ck < 8; ck++) {
    int st = ck & 1;
    if (ck < 7) { stage(ck + 1, st ^ 1); CP_COMMIT(); CP_WAIT1(); }
    else CP_WAIT0();
    __syncthreads();
    const __nv_bfloat16* MH = sm + st * PRJ_STAGE;
    const __nv_bfloat16* ML = MH + PRJ_M;
    const __nv_bfloat16* WH = ML + PRJ_M;
    const __nv_bfloat16* WL = WH + PRJ_W;
#pragma unroll
    for (int kb = 0; kb < 64; kb += 16) {
      uint32_t ah[2][4], al[2][4];
#pragma unroll
      for (int mt = 0; mt < 2; mt++) {
        ldsm4(ah[mt], MH + (m_w + mt * 16 + (g & 1) * 8 + rw) * LDSTRIDE + kb + (g >> 1) * 8);
        ldsm4(al[mt], ML + (m_w + mt * 16 + (g & 1) * 8 + rw) * LDSTRIDE + kb + (g >> 1) * 8);
      }
      uint32_t bh4[2][4], bl4[2][4];
#pragma unroll
      for (int p = 0; p < 2; p++) {
        ldsm4(bh4[p], WH + (n_w + p * 16 + (g >> 1) * 8 + rw) * LDSTRIDE + kb + (g & 1) * 8);
        ldsm4(bl4[p], WL + (n_w + p * 16 + (g >> 1) * 8 + rw) * LDSTRIDE + kb + (g & 1) * 8);
      }
#pragma unroll
      for (int mt = 0; mt < 2; mt++)
#pragma unroll
        for (int p = 0; p < 2; p++) {
          mma16816(c[mt][2 * p], ah[mt], bh4[p]);
          mma16816(c[mt][2 * p], ah[mt], bl4[p]);
          mma16816(c[mt][2 * p], al[mt], bh4[p]);
          mma16816(c[mt][2 * p + 1], ah[mt], bh4[p] + 2);
          mma16816(c[mt][2 * p + 1], ah[mt], bl4[p] + 2);
          mma16816(c[mt][2 * p + 1], al[mt], bh4[p] + 2);
        }
    }
    __syncthreads();
  }

#pragma unroll
  for (int mt = 0; mt < 2; mt++) {
#pragma unroll
    for (int nt = 0; nt < 4; nt++) {
      int row = m0 + m_w + mt * 16 + r;
      int col = n0 + n_w + nt * 8 + (lane & 3) * 2;
      float* dst = out + (size_t)row * 256 + col;
      *(float2*)dst = make_float2(c[mt][nt][0], c[mt][nt][1]);
      *(float2*)(dst + 8 * 256) = make_float2(c[mt][nt][2], c[mt][nt][3]);
    }
  }
}

// ---------------- launch -----------------------------------------------------
extern "C" void kernel_launch(void* const* d_in, const int* in_sizes, int n_in,
                              void* d_out, int out_size) {
  const float* x     = (const float*)d_in[0];
  const float* pe    = (const float*)d_in[1];
  const float* Wq    = (const float*)d_in[2];
  const float* Wk    = (const float*)d_in[3];
  const float* Wv    = (const float*)d_in[4];
  const float* bv    = (const float*)d_in[5];
  const float* Wpe   = (const float*)d_in[6];
  const float* bpe   = (const float*)d_in[7];
  const float* Wproj = (const float*)d_in[8];
  float* out = (float*)d_out;

  cudaFuncSetAttribute(qkv_mma, cudaFuncAttributeMaxDynamicSharedMemorySize,
                       GEMM_SMEM_BYTES);
  cudaFuncSetAttribute(scoresm, cudaFuncAttributeMaxDynamicSharedMemorySize,
                       SM_SMEM_BYTES);
  cudaFuncSetAttribute(avpes, cudaFuncAttributeMaxDynamicSharedMemorySize,
                       AVP_SMEM_BYTES);
  cudaFuncSetAttribute(proj_mma, cudaFuncAttributeMaxDynamicSharedMemorySize,
                       PRJ_SMEM_BYTES);

  prep_all<<<1536, 256>>>(x, Wq, Wk, Wv, Wproj);
  qkv_mma<<<dim3(32, 24), 256, GEMM_SMEM_BYTES>>>(bv);
  scoresm<<<dim3(64, 32), 256, SM_SMEM_BYTES>>>();
  avpes<<<1280, 256, AVP_SMEM_BYTES>>>(pe);
  merge_kernel<<<dim3(32, 32), 256>>>(Wpe, bpe);
  proj_mma<<<dim3(32, 4), 256, PRJ_SMEM_BYTES>>>(out);
}

// round 16
// speedup vs baseline: 1.0901x; 1.0272x over previous
#include <cuda_runtime.h>
#include <cuda_bf16.h>
#include <cstdint>

#define NSEQ 1024
#define DIM  256
#define HEADS 8
#define EDIM 512
#define HD   64
#define PEC  32
#define BH   32           // B*HEADS
#define ROWS 4096         // B*N

// ---------------- scratch (device globals; no runtime allocation) ----------
__device__ __nv_bfloat16 g_xh[ROWS * DIM], g_xl[ROWS * DIM];
__device__ __nv_bfloat16 g_wth[1536 * 256], g_wtl[1536 * 256];   // [n][k]
__device__ __nv_bfloat16 g_wpth[256 * 512], g_wptl[256 * 512];   // [n][k]
__device__ __nv_bfloat16 g_qh[BH * NSEQ * HD];
__device__ __nv_bfloat16 g_ql[BH * NSEQ * HD];
__device__ __nv_bfloat16 g_kh[BH * NSEQ * HD];
__device__ __nv_bfloat16 g_kl[BH * NSEQ * HD];
__device__ __nv_bfloat16 g_vth[BH * HD * NSEQ];   // transposed: [bh][d][n]
__device__ __nv_bfloat16 g_vtl[BH * HD * NSEQ];
__device__ __nv_bfloat16 g_attn_h[(size_t)BH * NSEQ * NSEQ];  // 64 MB
__device__ float g_oh[BH * NSEQ * HD];
__device__ float g_pes[BH * NSEQ * PEC];
__device__ __nv_bfloat16 g_mh[ROWS * EDIM], g_ml[ROWS * EDIM];

union B16x8 { __nv_bfloat16 h[8]; uint4 u; };
union B16x4 { __nv_bfloat16 h[4]; uint2 u; };
union B16x2 { __nv_bfloat16 h[2]; uint32_t u; };

__device__ __forceinline__ void split2(float x, __nv_bfloat16& h, __nv_bfloat16& l) {
  h = __float2bfloat16_rn(x);
  l = __float2bfloat16_rn(x - __bfloat162float(h));
}

// m16n8k16 bf16 mma with fp32 accumulate (row.col)
__device__ __forceinline__ void mma16816(float* c, const uint32_t* a,
                                         const uint32_t* b) {
  asm volatile(
      "mma.sync.aligned.m16n8k16.row.col.f32.bf16.bf16.f32 "
      "{%0,%1,%2,%3}, {%4,%5,%6,%7}, {%8,%9}, {%0,%1,%2,%3};"
      : "+f"(c[0]), "+f"(c[1]), "+f"(c[2]), "+f"(c[3])
      : "r"(a[0]), "r"(a[1]), "r"(a[2]), "r"(a[3]), "r"(b[0]), "r"(b[1]));
}

// ldmatrix x4: 4 8x8 b16 tiles; lane group g=lane>>3 supplies address of tile g
__device__ __forceinline__ void ldsm4(uint32_t* d, const __nv_bfloat16* p) {
  uint32_t a = (uint32_t)__cvta_generic_to_shared(p);
  asm volatile("ldmatrix.sync.aligned.m8n8.x4.shared.b16 {%0,%1,%2,%3}, [%4];"
               : "=r"(d[0]), "=r"(d[1]), "=r"(d[2]), "=r"(d[3]) : "r"(a));
}
// ldmatrix x4 transposed
__device__ __forceinline__ void ldsm4t(uint32_t* d, const __nv_bfloat16* p) {
  uint32_t a = (uint32_t)__cvta_generic_to_shared(p);
  asm volatile("ldmatrix.sync.aligned.m8n8.x4.trans.shared.b16 {%0,%1,%2,%3}, [%4];"
               : "=r"(d[0]), "=r"(d[1]), "=r"(d[2]), "=r"(d[3]) : "r"(a));
}

// 16B async copy gmem -> smem
__device__ __forceinline__ void cp16(__nv_bfloat16* smem_ptr, const __nv_bfloat16* gptr) {
  uint32_t s = (uint32_t)__cvta_generic_to_shared(smem_ptr);
  asm volatile("cp.async.cg.shared.global [%0], [%1], 16;" :: "r"(s), "l"(gptr));
}
#define CP_COMMIT() asm volatile("cp.async.commit_group;" ::: "memory")
#define CP_WAIT1()  asm volatile("cp.async.wait_group 1;" ::: "memory")
#define CP_WAIT0()  asm volatile("cp.async.wait_group 0;" ::: "memory")

#define LDSTRIDE 72   // bf16 units per SMEM row (64 data + 8 pad)
#define PSTRIDE 136   // bf16 units per SMEM row (128 data + 8 pad)
#define PJSTR 40      // bf16 units per pe smem row (32 data + 8 pad)
#define GEMM_SMEM_BYTES ((2 * 128 + 2 * 64) * LDSTRIDE * 2)   // 55296

// ---------------- prep: split x + transpose/split weights (fused) -----------
__global__ __launch_bounds__(256) void prep_all(
    const float* __restrict__ x, const float* __restrict__ Wq,
    const float* __restrict__ Wk, const float* __restrict__ Wv,
    const float* __restrict__ Wproj) {
  if (blockIdx.x < 1024) {
    int idx = (blockIdx.x * 256 + threadIdx.x) * 4;
    float4 v = *(const float4*)(x + idx);
    B16x4 hh, ll;
    split2(v.x, hh.h[0], ll.h[0]); split2(v.y, hh.h[1], ll.h[1]);
    split2(v.z, hh.h[2], ll.h[2]); split2(v.w, hh.h[3], ll.h[3]);
    *(uint2*)&g_xh[idx] = hh.u;
    *(uint2*)&g_xl[idx] = ll.u;
    return;
  }
  int id = (blockIdx.x - 1024) * 256 + threadIdx.x;
  if (id < 98304) {                 // WT: 1536 n x 64 k-groups
    int n = id >> 6, k0 = (id & 63) * 4;
    int sel = n >> 9, col = n & 511;
    const float* W = (sel == 0) ? Wq : (sel == 1) ? Wk : Wv;
#pragma unroll
    for (int q = 0; q < 4; q++) {
      float v = W[(k0 + q) * 512 + col];
      split2(v, g_wth[n * 256 + k0 + q], g_wtl[n * 256 + k0 + q]);
    }
  } else {                          // WprojT: 256 n x 128 k-groups
    int id2 = id - 98304;
    int n = id2 >> 7, k0 = (id2 & 127) * 4;
#pragma unroll
    for (int q = 0; q < 4; q++) {
      float v = Wproj[(k0 + q) * 256 + n];
      split2(v, g_wpth[n * 512 + k0 + q], g_wptl[n * 512 + k0 + q]);
    }
  }
}

// ---------------- Kernel 1: QKV projection via mma.sync ---------------------
// M=4096, N=1536, K=256. CTA 128m x 64n, grid (32, 24). 8 warps: 4m x 2n.
__global__ __launch_bounds__(256) void qkv_mma(const float* __restrict__ bv) {
  extern __shared__ __nv_bfloat16 sm[];
  __nv_bfloat16* XH = sm;
  __nv_bfloat16* XL = XH + 128 * LDSTRIDE;
  __nv_bfloat16* WH = XL + 128 * LDSTRIDE;
  __nv_bfloat16* WL = WH + 64 * LDSTRIDE;

  int tid = threadIdx.x;
  int wid = tid >> 5, lane = tid & 31;
  int m0 = blockIdx.x * 128;
  int n0 = blockIdx.y * 64;
  int sel = n0 / 512;
  int e0 = n0 % 512;
  int h = e0 / 64;

  int m_w = (wid >> 1) * 32, n_w = (wid & 1) * 32;
  int r = lane >> 2;
  int g = lane >> 3, rw = lane & 7;

  float c[2][4][4];
#pragma unroll
  for (int mt = 0; mt < 2; mt++)
#pragma unroll
    for (int nt = 0; nt < 4; nt++)
#pragma unroll
      for (int e = 0; e < 4; e++) c[mt][nt][e] = 0.f;

  for (int ck = 0; ck < 4; ck++) {
    if (ck) __syncthreads();
#pragma unroll
    for (int t = 0; t < 4; t++) {
      int idx = tid + 256 * t;
      int rr = idx >> 3, seg = idx & 7;
      int so = rr * LDSTRIDE + seg * 8;
      size_t gs = (size_t)(m0 + rr) * 256 + ck * 64 + seg * 8;
      *(uint4*)(XH + so) = *(const uint4*)(g_xh + gs);
      *(uint4*)(XL + so) = *(const uint4*)(g_xl + gs);
    }
#pragma unroll
    for (int t = 0; t < 2; t++) {
      int idx = tid + 256 * t;
      int d = idx >> 3, seg = idx & 7;
      int so = d * LDSTRIDE + seg * 8;
      size_t gs = (size_t)(n0 + d) * 256 + ck * 64 + seg * 8;
      *(uint4*)(WH + so) = *(const uint4*)(g_wth + gs);
      *(uint4*)(WL + so) = *(const uint4*)(g_wtl + gs);
    }
    __syncthreads();
#pragma unroll
    for (int kb = 0; kb < 64; kb += 16) {
      uint32_t ah[2][4], al[2][4];
#pragma unroll
      for (int mt = 0; mt < 2; mt++) {
        ldsm4(ah[mt], XH + (m_w + mt * 16 + (g & 1) * 8 + rw) * LDSTRIDE + kb + (g >> 1) * 8);
        ldsm4(al[mt], XL + (m_w + mt * 16 + (g & 1) * 8 + rw) * LDSTRIDE + kb + (g >> 1) * 8);
      }
      uint32_t bh4[2][4], bl4[2][4];
#pragma unroll
      for (int p = 0; p < 2; p++) {
        ldsm4(bh4[p], WH + (n_w + p * 16 + (g >> 1) * 8 + rw) * LDSTRIDE + kb + (g & 1) * 8);
        ldsm4(bl4[p], WL + (n_w + p * 16 + (g >> 1) * 8 + rw) * LDSTRIDE + kb + (g & 1) * 8);
      }
#pragma unroll
      for (int mt = 0; mt < 2; mt++)
#pragma unroll
        for (int p = 0; p < 2; p++) {
          mma16816(c[mt][2 * p], ah[mt], bh4[p]);
          mma16816(c[mt][2 * p], ah[mt], bl4[p]);
          mma16816(c[mt][2 * p], al[mt], bh4[p]);
          mma16816(c[mt][2 * p + 1], ah[mt], bh4[p] + 2);
          mma16816(c[mt][2 * p + 1], ah[mt], bl4[p] + 2);
          mma16816(c[mt][2 * p + 1], al[mt], bh4[p] + 2);
        }
    }
  }

#pragma unroll
  for (int mt = 0; mt < 2; mt++) {
#pragma unroll
    for (int nt = 0; nt < 4; nt++) {
      int colw = n_w + nt * 8 + (lane & 3) * 2;   // 0..62, even
      int d = colw;                                // channel within head
      int e = e0 + colw;
#pragma unroll
      for (int half = 0; half < 2; half++) {
        int row = m0 + m_w + mt * 16 + r + half * 8;
        float v0 = c[mt][nt][half * 2 + 0];
        float v1 = c[mt][nt][half * 2 + 1];
        int b = row >> 10, n = row & 1023;
        int bh = b * 8 + h;
        if (sel == 0) {
          v0 *= 0.125f; v1 *= 0.125f;
          B16x2 hp, lp;
          split2(v0, hp.h[0], lp.h[0]); split2(v1, hp.h[1], lp.h[1]);
          size_t idx = ((size_t)bh * 1024 + n) * 64 + d;
          *(uint32_t*)&g_qh[idx] = hp.u;
          *(uint32_t*)&g_ql[idx] = lp.u;
        } else if (sel == 1) {
          B16x2 hp, lp;
          split2(v0, hp.h[0], lp.h[0]); split2(v1, hp.h[1], lp.h[1]);
          size_t idx = ((size_t)bh * 1024 + n) * 64 + d;
          *(uint32_t*)&g_kh[idx] = hp.u;
          *(uint32_t*)&g_kl[idx] = lp.u;
        } else {
          v0 += bv[e]; v1 += bv[e + 1];
          __nv_bfloat16 hh, ll;
          split2(v0, hh, ll);
          size_t i0v = ((size_t)bh * 64 + d) * 1024 + n;
          g_vth[i0v] = hh; g_vtl[i0v] = ll;
          split2(v1, hh, ll);
          size_t i1v = ((size_t)bh * 64 + d + 1) * 1024 + n;
          g_vth[i1v] = hh; g_vtl[i1v] = ll;
        }
      }
    }
  }
}

// ---------------- Kernel 2: fused scores + softmax (16-row CTAs) ------------
#define KSTAGE (128 * LDSTRIDE)     // 9216 elements per K stage
#define SM_SMEM_BYTES ((2 * 16 * LDSTRIDE + 2 * KSTAGE) * 2)   // 41472 B
__global__ __launch_bounds__(256, 2) void scoresm() {
  extern __shared__ __nv_bfloat16 smd[];
  __nv_bfloat16* QH = smd;
  __nv_bfloat16* QL = QH + 16 * LDSTRIDE;
  __nv_bfloat16* KHb = QL + 16 * LDSTRIDE;   // 2 stages of KSTAGE
  __shared__ float red[16][8];

  int tid = threadIdx.x;
  int wid = tid >> 5, lane = tid & 31;
  int bh = blockIdx.y;
  int i0 = blockIdx.x * 16;

  const __nv_bfloat16* qh = g_qh + (size_t)bh * NSEQ * HD;
  const __nv_bfloat16* ql = g_ql + (size_t)bh * NSEQ * HD;
  const __nv_bfloat16* kh = g_kh + (size_t)bh * NSEQ * HD;

  if (tid < 128) {
    int r = tid >> 3, seg = tid & 7;
    int so = r * LDSTRIDE + seg * 8;
    *(uint4*)(QH + so) = *(const uint4*)(qh + (i0 + r) * 64 + seg * 8);
    *(uint4*)(QL + so) = *(const uint4*)(ql + (i0 + r) * 64 + seg * 8);
  }
#pragma unroll
  for (int t = 0; t < 4; t++) {
    int idx = tid + 256 * t;
    int rr = idx >> 3, seg = idx & 7;
    cp16(KHb + rr * LDSTRIDE + seg * 8, kh + rr * 64 + seg * 8);
  }
  CP_COMMIT();

  int nwb = wid * 16;
  int r = lane >> 2;
  int g = lane >> 3, rw = lane & 7;

  uint32_t ah[4][4], al[4][4];
  float acc[8][2][4];
#pragma unroll
  for (int jc = 0; jc < 8; jc++)
#pragma unroll
    for (int nt = 0; nt < 2; nt++)
#pragma unroll
      for (int e = 0; e < 4; e++) acc[jc][nt][e] = 0.f;

#pragma unroll
  for (int jc = 0; jc < 8; jc++) {
    int st = jc & 1;
    if (jc < 7) {
      int sn = st ^ 1;
#pragma unroll
      for (int t = 0; t < 4; t++) {
        int idx = tid + 256 * t;
        int rr = idx >> 3, seg = idx & 7;
        cp16(KHb + sn * KSTAGE + rr * LDSTRIDE + seg * 8,
             kh + ((jc + 1) * 128 + rr) * 64 + seg * 8);
      }
      CP_COMMIT();
      CP_WAIT1();
    } else {
      CP_WAIT0();
    }
    __syncthreads();
    const __nv_bfloat16* KH = KHb + st * KSTAGE;
    if (jc == 0) {
#pragma unroll
      for (int kb = 0; kb < 4; kb++) {
        ldsm4(ah[kb], QH + ((g & 1) * 8 + rw) * LDSTRIDE + kb * 16 + (g >> 1) * 8);
        ldsm4(al[kb], QL + ((g & 1) * 8 + rw) * LDSTRIDE + kb * 16 + (g >> 1) * 8);
      }
    }
#pragma unroll
    for (int kb = 0; kb < 4; kb++) {
      uint32_t b4[4];
      ldsm4(b4, KH + (nwb + (g >> 1) * 8 + rw) * LDSTRIDE + kb * 16 + (g & 1) * 8);
      mma16816(acc[jc][0], ah[kb], b4);
      mma16816(acc[jc][0], al[kb], b4);
      mma16816(acc[jc][1], ah[kb], b4 + 2);
      mma16816(acc[jc][1], al[kb], b4 + 2);
    }
    __syncthreads();
  }

  int r0 = r, r1 = r0 + 8;
  float m0 = -1e30f, m1 = -1e30f;
#pragma unroll
  for (int jc = 0; jc < 8; jc++)
#pragma unroll
    for (int nt = 0; nt < 2; nt++) {
      m0 = fmaxf(m0, fmaxf(acc[jc][nt][0], acc[jc][nt][1]));
      m1 = fmaxf(m1, fmaxf(acc[jc][nt][2], acc[jc][nt][3]));
    }
#pragma unroll
  for (int o = 1; o <= 2; o <<= 1) {
    m0 = fmaxf(m0, __shfl_xor_sync(~0u, m0, o));
    m1 = fmaxf(m1, __shfl_xor_sync(~0u, m1, o));
  }
  if ((lane & 3) == 0) { red[r0][wid] = m0; red[r1][wid] = m1; }
  __syncthreads();
#pragma unroll
  for (int q = 0; q < 8; q++) {
    m0 = fmaxf(m0, red[r0][q]);
    m1 = fmaxf(m1, red[r1][q]);
  }
  __syncthreads();

  float s0 = 0.f, s1 = 0.f;
#pragma unroll
  for (int jc = 0; jc < 8; jc++)
#pragma unroll
    for (int nt = 0; nt < 2; nt++) {
      acc[jc][nt][0] = __expf(acc[jc][nt][0] - m0);
      acc[jc][nt][1] = __expf(acc[jc][nt][1] - m0);
      acc[jc][nt][2] = __expf(acc[jc][nt][2] - m1);
      acc[jc][nt][3] = __expf(acc[jc][nt][3] - m1);
      s0 += acc[jc][nt][0] + acc[jc][nt][1];
      s1 += acc[jc][nt][2] + acc[jc][nt][3];
    }
#pragma unroll
  for (int o = 1; o <= 2; o <<= 1) {
    s0 += __shfl_xor_sync(~0u, s0, o);
    s1 += __shfl_xor_sync(~0u, s1, o);
  }
  if ((lane & 3) == 0) { red[r0][wid] = s0; red[r1][wid] = s1; }
  __syncthreads();
  s0 = 0.f; s1 = 0.f;
#pragma unroll
  for (int q = 0; q < 8; q++) { s0 += red[r0][q]; s1 += red[r1][q]; }
  float inv0 = 1.f / s0, inv1 = 1.f / s1;

  size_t base0 = (((size_t)bh << 10) + (i0 + r0)) << 10;
  size_t base1 = (((size_t)bh << 10) + (i0 + r1)) << 10;
#pragma unroll
  for (int jc = 0; jc < 8; jc++) {
#pragma unroll
    for (int nt = 0; nt < 2; nt++) {
      int col = jc * 128 + nwb + nt * 8 + (lane & 3) * 2;
      B16x2 hp;
      hp.h[0] = __float2bfloat16_rn(acc[jc][nt][0] * inv0);
      hp.h[1] = __float2bfloat16_rn(acc[jc][nt][1] * inv0);
      *(uint32_t*)(g_attn_h + base0 + col) = hp.u;
      hp.h[0] = __float2bfloat16_rn(acc[jc][nt][2] * inv1);
      hp.h[1] = __float2bfloat16_rn(acc[jc][nt][3] * inv1);
      *(uint32_t*)(g_attn_h + base1 + col) = hp.u;
    }
  }
}

// ---------------- Kernel 3: FUSED av + pes (contiguous blocks) --------------
#define AV_A (128 * LDSTRIDE)   // 9216
#define AV_V (64 * LDSTRIDE)    // 4608
#define AV_STAGE (AV_A + 2 * AV_V)       // 18432 elements per stage
#define AVP_SMEM_BYTES (2 * AV_STAGE * 2) // 73728 B
__global__ __launch_bounds__(256, 2) void avpes(const float* __restrict__ pe) {
  extern __shared__ __nv_bfloat16 smd[];
  int tid = threadIdx.x;
  int wid = tid >> 5, lane = tid & 31;

  if (blockIdx.x < 256) {
    // =================== AV body ===================
    int bh = blockIdx.x >> 3;
    int i0 = (blockIdx.x & 7) * 128;

    const __nv_bfloat16* vth = g_vth + (size_t)bh * HD * NSEQ;
    const __nv_bfloat16* vtl = g_vtl + (size_t)bh * HD * NSEQ;

    int m_w = (wid >> 1) * 32;
    int n_w = (wid & 1) * 32;
    int r = lane >> 2;
    int g = lane >> 3, rw = lane & 7;

    float c[2][4][4];
#pragma unroll
    for (int mt = 0; mt < 2; mt++)
#pragma unroll
      for (int nt = 0; nt < 4; nt++)
#pragma unroll
        for (int e = 0; e < 4; e++) c[mt][nt][e] = 0.f;

#pragma unroll
    for (int t = 0; t < 4; t++) {
      int idx = tid + 256 * t;
      int rr = idx >> 3, seg = idx & 7;
      size_t gsrc = ((((size_t)bh << 10) + i0 + rr) << 10) + seg * 8;
      cp16(smd + rr * LDSTRIDE + seg * 8, g_attn_h + gsrc);
    }
#pragma unroll
    for (int t = 0; t < 2; t++) {
      int idx = tid + 256 * t;
      int d = idx >> 3, seg = idx & 7;
      int so = AV_A + d * LDSTRIDE + seg * 8;
      cp16(smd + so, vth + (size_t)d * 1024 + seg * 8);
      cp16(smd + AV_V + so, vtl + (size_t)d * 1024 + seg * 8);
    }
    CP_COMMIT();

    for (int ck = 0; ck < 16; ck++) {
      int st = ck & 1;
      if (ck < 15) {
        int sn = st ^ 1;
        __nv_bfloat16* base = smd + sn * AV_STAGE;
#pragma unroll
        for (int t = 0; t < 4; t++) {
          int idx = tid + 256 * t;
          int rr = idx >> 3, seg = idx & 7;
          size_t gsrc = ((((size_t)bh << 10) + i0 + rr) << 10) + (ck + 1) * 64 + seg * 8;
          cp16(base + rr * LDSTRIDE + seg * 8, g_attn_h + gsrc);
        }
#pragma unroll
        for (int t = 0; t < 2; t++) {
          int idx = tid + 256 * t;
          int d = idx >> 3, seg = idx & 7;
          int so = AV_A + d * LDSTRIDE + seg * 8;
          cp16(base + so, vth + (size_t)d * 1024 + (ck + 1) * 64 + seg * 8);
          cp16(base + AV_V + so, vtl + (size_t)d * 1024 + (ck + 1) * 64 + seg * 8);
        }
        CP_COMMIT();
        CP_WAIT1();
      } else {
        CP_WAIT0();
      }
      __syncthreads();
      const __nv_bfloat16* AHs = smd + st * AV_STAGE;
      const __nv_bfloat16* VHs = AHs + AV_A;
      const __nv_bfloat16* VLs = VHs + AV_V;

#pragma unroll
      for (int kb = 0; kb < 64; kb += 16) {
        uint32_t ah[2][4];
#pragma unroll
        for (int mt = 0; mt < 2; mt++)
          ldsm4(ah[mt], AHs + (m_w + mt * 16 + (g & 1) * 8 + rw) * LDSTRIDE + kb + (g >> 1) * 8);
        uint32_t bh4[2][4], bl4[2][4];
#pragma unroll
        for (int p = 0; p < 2; p++) {
          ldsm4(bh4[p], VHs + (n_w + p * 16 + (g >> 1) * 8 + rw) * LDSTRIDE + kb + (g & 1) * 8);
          ldsm4(bl4[p], VLs + (n_w + p * 16 + (g >> 1) * 8 + rw) * LDSTRIDE + kb + (g & 1) * 8);
        }
#pragma unroll
        for (int mt = 0; mt < 2; mt++)
#pragma unroll
          for (int p = 0; p < 2; p++) {
            mma16816(c[mt][2 * p], ah[mt], bh4[p]);
            mma16816(c[mt][2 * p], ah[mt], bl4[p]);
            mma16816(c[mt][2 * p + 1], ah[mt], bh4[p] + 2);
            mma16816(c[mt][2 * p + 1], ah[mt], bl4[p] + 2);
          }
      }
      __syncthreads();
    }

#pragma unroll
    for (int mt = 0; mt < 2; mt++) {
#pragma unroll
      for (int nt = 0; nt < 4; nt++) {
        int row = i0 + m_w + mt * 16 + r;
        int col = n_w + nt * 8 + (lane & 3) * 2;
        float* dst = g_oh + ((size_t)bh * 1024 + row) * 64 + col;
        *(float2*)dst = make_float2(c[mt][nt][0], c[mt][nt][1]);
        *(float2*)(dst + 8 * 64) = make_float2(c[mt][nt][2], c[mt][nt][3]);
      }
    }
  } else {
    // =================== PES body ===================
    int i = blockIdx.x - 256;
    __nv_bfloat16* AH0 = smd;                       // 2 stages of 32*PSTRIDE
    __nv_bfloat16* PJ0 = smd + 2 * 32 * PSTRIDE;    // 2 stages of 128*PJSTR ([j][c])

    int mw = (wid & 1) * 16;        // bh rows
    int nw = (wid >> 1) * 8;        // c cols
    int r = lane >> 2;
    int g = lane >> 3, rw = lane & 7;

#pragma unroll
    for (int t = 0; t < 2; t++) {
      int idx = tid + 256 * t;
      int row = idx >> 4, seg = idx & 15;
      size_t gsrc = ((size_t)row << 20) + ((size_t)i << 10) + seg * 8;
      cp16(AH0 + row * PSTRIDE + seg * 8, g_attn_h + gsrc);
    }
    CP_COMMIT();
    float4 pv[4];
#pragma unroll
    for (int t = 0; t < 4; t++) {
      int idx = tid + 256 * t;
      int j = idx >> 3, c4 = idx & 7;
      pv[t] = *(const float4*)(pe + (((size_t)i << 10) + j) * 32 + c4 * 4);
    }

    float acc[4] = {};
    for (int kc = 0; kc < 8; kc++) {
      int st = kc & 1;
      if (kc < 7) {
        __nv_bfloat16* AHn = AH0 + (st ^ 1) * 32 * PSTRIDE;
#pragma unroll
        for (int t = 0; t < 2; t++) {
          int idx = tid + 256 * t;
          int row = idx >> 4, seg = idx & 15;
          size_t gsrc = ((size_t)row << 20) + ((size_t)i << 10) + (kc + 1) * 128 + seg * 8;
          cp16(AHn + row * PSTRIDE + seg * 8, g_attn_h + gsrc);
        }
        CP_COMMIT();
      }
      // store prefetched pe regs to PJ[st] in NATURAL [j][c] layout (vectorized)
      __nv_bfloat16* PJs = PJ0 + st * 128 * PJSTR;
#pragma unroll
      for (int t = 0; t < 4; t++) {
        int idx = tid + 256 * t;
        int j = idx >> 3, c4 = idx & 7;
        B16x4 b;
        b.h[0] = __float2bfloat16_rn(pv[t].x);
        b.h[1] = __float2bfloat16_rn(pv[t].y);
        b.h[2] = __float2bfloat16_rn(pv[t].z);
        b.h[3] = __float2bfloat16_rn(pv[t].w);
        *(uint2*)(PJs + j * PJSTR + c4 * 4) = b.u;
      }
      if (kc < 7) {
#pragma unroll
        for (int t = 0; t < 4; t++) {
          int idx = tid + 256 * t;
          int j = idx >> 3, c4 = idx & 7;
          pv[t] = *(const float4*)(
              pe + (((size_t)i << 10) + (kc + 1) * 128 + j) * 32 + c4 * 4);
        }
      }
      if (kc < 7) CP_WAIT1(); else CP_WAIT0();
      __syncthreads();
      const __nv_bfloat16* AHs = AH0 + st * 32 * PSTRIDE;
#pragma unroll
      for (int kb = 0; kb < 8; kb += 2) {
        uint32_t a0[4], a1[4], b4[4];
        ldsm4(a0, AHs + (mw + (g & 1) * 8 + rw) * PSTRIDE + kb * 16 + (g >> 1) * 8);
        ldsm4(a1, AHs + (mw + (g & 1) * 8 + rw) * PSTRIDE + (kb + 1) * 16 + (g >> 1) * 8);
        // trans-load b frags for kb (r0,r1) and kb+1 (r2,r3): rows = j
        ldsm4t(b4, PJs + (kb * 16 + g * 8 + rw) * PJSTR + nw);
        mma16816(acc, a0, b4);
        mma16816(acc, a1, b4 + 2);
      }
      __syncthreads();
    }
    int c = nw + (lane & 3) * 2;
    int b0 = mw + r, b1 = b0 + 8;
    *(float2*)&g_pes[(((size_t)b0 << 10) + i) * 32 + c] = make_float2(acc[0], acc[1]);
    *(float2*)&g_pes[(((size_t)b1 << 10) + i) * 32 + c] = make_float2(acc[2], acc[3]);
  }
}

// ---------------- Kernel 4: merged = out_head + pe_sum@Wpe + bpe (split) ----
__global__ __launch_bounds__(256) void merge_kernel(
    const float* __restrict__ Wpe, const float* __restrict__ bpe) {
  __shared__ float wpe_s[32 * 64];
  __shared__ float pes_s[32 * 32];
  __shared__ float bpe_s[64];
  int bh = blockIdx.x;
  int n0 = blockIdx.y * 32;
  int tid = threadIdx.x;
#pragma unroll
  for (int r = 0; r < 8; r++) wpe_s[tid + r * 256] = Wpe[tid + r * 256];
  if (tid < 64) bpe_s[tid] = bpe[tid];
  {
    int nl = tid >> 3, cc = tid & 7;
    *(float4*)&pes_s[nl * 32 + cc * 4] =
        *(const float4*)(g_pes + ((size_t)bh * 1024 + n0 + nl) * 32 + cc * 4);
  }
  __syncthreads();
  int nl = tid >> 3;
  int d0 = (tid & 7) * 8;
  int b = bh >> 3, h = bh & 7;
  const float* ohp = g_oh + ((size_t)bh * 1024 + n0 + nl) * 64 + d0;
  float o[8];
#pragma unroll
  for (int dd = 0; dd < 8; dd++) o[dd] = bpe_s[d0 + dd] + ohp[dd];
#pragma unroll 8
  for (int c = 0; c < 32; c++) {
    float pv = pes_s[nl * 32 + c];
#pragma unroll
    for (int dd = 0; dd < 8; dd++) o[dd] += pv * wpe_s[c * 64 + d0 + dd];
  }
  size_t mp = ((size_t)(b * 1024 + n0 + nl)) * 512 + h * 64 + d0;
  B16x8 hh, ll;
#pragma unroll
  for (int dd = 0; dd < 8; dd++) split2(o[dd], hh.h[dd], ll.h[dd]);
  *(uint4*)&g_mh[mp] = hh.u;
  *(uint4*)&g_ml[mp] = ll.u;
}

// ---------------- Kernel 5: out = merged @ Wproj (cp.async pipelined) -------
// M=4096, N=256, K=512. CTA 128m x 64n, grid (32, 4). Single wave.
#define PRJ_M (128 * LDSTRIDE)
#define PRJ_W (64 * LDSTRIDE)
#define PRJ_STAGE (2 * PRJ_M + 2 * PRJ_W)     // 27648
#define PRJ_SMEM_BYTES (2 * PRJ_STAGE * 2)    // 110592
__global__ __launch_bounds__(256) void proj_mma(float* __restrict__ out) {
  extern __shared__ __nv_bfloat16 sm[];

  int tid = threadIdx.x;
  int wid = tid >> 5, lane = tid & 31;
  int m0 = blockIdx.x * 128;
  int n0 = blockIdx.y * 64;

  int m_w = (wid >> 1) * 32, n_w = (wid & 1) * 32;
  int r = lane >> 2;
  int g = lane >> 3, rw = lane & 7;

  auto stage = [&](int ck, int s) {
    __nv_bfloat16* base = sm + s * PRJ_STAGE;
#pragma unroll
    for (int t = 0; t < 4; t++) {
      int idx = tid + 256 * t;
      int rr = idx >> 3, seg = idx & 7;
      int so = rr * LDSTRIDE + seg * 8;
      size_t gs = (size_t)(m0 + rr) * 512 + ck * 64 + seg * 8;
      cp16(base + so, g_mh + gs);
      cp16(base + PRJ_M + so, g_ml + gs);
    }
#pragma unroll
    for (int t = 0; t < 2; t++) {
      int idx = tid + 256 * t;
      int d = idx >> 3, seg = idx & 7;
      int so = 2 * PRJ_M + d * LDSTRIDE + seg * 8;
      size_t gs = (size_t)(n0 + d) * 512 + ck * 64 + seg * 8;
      cp16(base + so, g_wpth + gs);
      cp16(base + PRJ_W + so, g_wptl + gs);
    }
  };

  float c[2][4][4];
#pragma unroll
  for (int mt = 0; mt < 2; mt++)
#pragma unroll
    for (int nt = 0; nt < 4; nt++)
#pragma unroll
      for (int e = 0; e < 4; e++) c[mt][nt][e] = 0.f;

  stage(0, 0);
  CP_COMMIT();

  for (int ck = 0; ck < 8; ck++) {
    int st = ck & 1;
    if (ck < 7) { stage(ck + 1, st ^ 1); CP_COMMIT(); CP_WAIT1(); }
    else CP_WAIT0();
    __syncthreads();
    const __nv_bfloat16* MH = sm + st * PRJ_STAGE;
    const __nv_bfloat16* ML = MH + PRJ_M;
    const __nv_bfloat16* WH = ML + PRJ_M;
    const __nv_bfloat16* WL = WH + PRJ_W;
#pragma unroll
    for (int kb = 0; kb < 64; kb += 16) {
      uint32_t ah[2][4], al[2][4];
#pragma unroll
      for (int mt = 0; mt < 2; mt++) {
        ldsm4(ah[mt], MH + (m_w + mt * 16 + (g & 1) * 8 + rw) * LDSTRIDE + kb + (g >> 1) * 8);
        ldsm4(al[mt], ML + (m_w + mt * 16 + (g & 1) * 8 + rw) * LDSTRIDE + kb + (g >> 1) * 8);
      }
      uint32_t bh4[2][4], bl4[2][4];
#pragma unroll
      for (int p = 0; p < 2; p++) {
        ldsm4(bh4[p], WH + (n_w + p * 16 + (g >> 1) * 8 + rw) * LDSTRIDE + kb + (g & 1) * 8);
        ldsm4(bl4[p], WL + (n_w + p * 16 + (g >> 1) * 8 + rw) * LDSTRIDE + kb + (g & 1) * 8);
      }
#pragma unroll
      for (int mt = 0; mt < 2; mt++)
#pragma unroll
        for (int p = 0; p < 2; p++) {
          mma16816(c[mt][2 * p], ah[mt], bh4[p]);
          mma16816(c[mt][2 * p], ah[mt], bl4[p]);
          mma16816(c[mt][2 * p], al[mt], bh4[p]);
          mma16816(c[mt][2 * p + 1], ah[mt], bh4[p] + 2);
          mma16816(c[mt][2 * p + 1], ah[mt], bl4[p] + 2);
          mma16816(c[mt][2 * p + 1], al[mt], bh4[p] + 2);
        }
    }
    __syncthreads();
  }

#pragma unroll
  for (int mt = 0; mt < 2; mt++) {
#pragma unroll
    for (int nt = 0; nt < 4; nt++) {
      int row = m0 + m_w + mt * 16 + r;
      int col = n0 + n_w + nt * 8 + (lane & 3) * 2;
      float* dst = out + (size_t)row * 256 + col;
      *(float2*)dst = make_float2(c[mt][nt][0], c[mt][nt][1]);
      *(float2*)(dst + 8 * 256) = make_float2(c[mt][nt][2], c[mt][nt][3]);
    }
  }
}

// ---------------- launch -----------------------------------------------------
extern "C" void kernel_launch(void* const* d_in, const int* in_sizes, int n_in,
                              void* d_out, int out_size) {
  const float* x     = (const float*)d_in[0];
  const float* pe    = (const float*)d_in[1];
  const float* Wq    = (const float*)d_in[2];
  const float* Wk    = (const float*)d_in[3];
  const float* Wv    = (const float*)d_in[4];
  const float* bv    = (const float*)d_in[5];
  const float* Wpe   = (const float*)d_in[6];
  const float* bpe   = (const float*)d_in[7];
  const float* Wproj = (const float*)d_in[8];
  float* out = (float*)d_out;

  cudaFuncSetAttribute(qkv_mma, cudaFuncAttributeMaxDynamicSharedMemorySize,
                       GEMM_SMEM_BYTES);
  cudaFuncSetAttribute(scoresm, cudaFuncAttributeMaxDynamicSharedMemorySize,
                       SM_SMEM_BYTES);
  cudaFuncSetAttribute(avpes, cudaFuncAttributeMaxDynamicSharedMemorySize,
                       AVP_SMEM_BYTES);
  cudaFuncSetAttribute(proj_mma, cudaFuncAttributeMaxDynamicSharedMemorySize,
                       PRJ_SMEM_BYTES);

  prep_all<<<1536, 256>>>(x, Wq, Wk, Wv, Wproj);
  qkv_mma<<<dim3(32, 24), 256, GEMM_SMEM_BYTES>>>(bv);
  scoresm<<<dim3(64, 32), 256, SM_SMEM_BYTES>>>();
  avpes<<<1280, 256, AVP_SMEM_BYTES>>>(pe);
  merge_kernel<<<dim3(32, 32), 256>>>(Wpe, bpe);
  proj_mma<<<dim3(32, 4), 256, PRJ_SMEM_BYTES>>>(out);
}